// round 4
// baseline (speedup 1.0000x reference)
#include <cuda_runtime.h>
#include <cuda_bf16.h>
#include <math.h>
#include <stdint.h>

// ============================================================================
// PaddedSHCSA via mma.sync bf16 split hi/lo 3-pass. Round 4: 4-stage cp.async
// pipeline, prefetch-before-compute, single syncthreads per chunk.
// ============================================================================

#define S_DIM   4096
#define F_DIM   2048
#define F3_DIM  6144

__device__ __nv_bfloat16 g_xh [(size_t)S_DIM * F_DIM];
__device__ __nv_bfloat16 g_xl [(size_t)S_DIM * F_DIM];
__device__ __nv_bfloat16 g_Wth[(size_t)F3_DIM * F_DIM];   // W^T [3F][F]
__device__ __nv_bfloat16 g_Wtl[(size_t)F3_DIM * F_DIM];
__device__ __nv_bfloat16 g_qh [(size_t)S_DIM * F_DIM];
__device__ __nv_bfloat16 g_ql [(size_t)S_DIM * F_DIM];
__device__ __nv_bfloat16 g_kh [(size_t)S_DIM * F_DIM];
__device__ __nv_bfloat16 g_kl [(size_t)S_DIM * F_DIM];
__device__ __nv_bfloat16 g_vTh[(size_t)F_DIM * S_DIM];    // v^T [F][S]
__device__ __nv_bfloat16 g_vTl[(size_t)F_DIM * S_DIM];
__device__ float         g_scores[(size_t)S_DIM * S_DIM];
__device__ __nv_bfloat16 g_atth[(size_t)S_DIM * S_DIM];
__device__ __nv_bfloat16 g_attl[(size_t)S_DIM * S_DIM];

// ---------------- low-level helpers -----------------------------------------
__device__ __forceinline__ uint32_t smem_u32(const void* p) {
    uint32_t a;
    asm("{ .reg .u64 t; cvta.to.shared.u64 t, %1; cvt.u32.u64 %0, t; }" : "=r"(a) : "l"(p));
    return a;
}
#define CP_ASYNC16(dst_u32, src_ptr) \
    asm volatile("cp.async.cg.shared.global [%0], [%1], 16;" :: "r"(dst_u32), "l"(src_ptr))
#define CP_COMMIT()  asm volatile("cp.async.commit_group;" ::: "memory")
#define CP_WAIT2()   asm volatile("cp.async.wait_group 2;" ::: "memory")
#define CP_WAIT0()   asm volatile("cp.async.wait_group 0;" ::: "memory")

__device__ __forceinline__ void ldsm_x4(uint32_t* r, uint32_t addr) {
    asm volatile("ldmatrix.sync.aligned.m8n8.x4.shared.b16 {%0,%1,%2,%3}, [%4];"
        : "=r"(r[0]), "=r"(r[1]), "=r"(r[2]), "=r"(r[3]) : "r"(addr));
}
__device__ __forceinline__ void ldsm_x2(uint32_t* r, uint32_t addr) {
    asm volatile("ldmatrix.sync.aligned.m8n8.x2.shared.b16 {%0,%1}, [%2];"
        : "=r"(r[0]), "=r"(r[1]) : "r"(addr));
}
__device__ __forceinline__ void mma16816(float* c, const uint32_t* a, const uint32_t* b) {
    asm volatile("mma.sync.aligned.m16n8k16.row.col.f32.bf16.bf16.f32 "
        "{%0,%1,%2,%3}, {%4,%5,%6,%7}, {%8,%9}, {%0,%1,%2,%3};"
        : "+f"(c[0]), "+f"(c[1]), "+f"(c[2]), "+f"(c[3])
        : "r"(a[0]), "r"(a[1]), "r"(a[2]), "r"(a[3]), "r"(b[0]), "r"(b[1]));
}
__device__ __forceinline__ void split_bf16(float v, __nv_bfloat16& h, __nv_bfloat16& l) {
    h = __float2bfloat16(v);
    l = __float2bfloat16(v - __bfloat162float(h));
}

// ---------------- smem layout -----------------------------------------------
static constexpr int PA = 40;                       // pitch in halves
static constexpr int TILE_B = 128 * PA * 2;         // 10240 B
static constexpr int STAGE_B = 4 * TILE_B;          // 40960 B (Ah Al Bh Bl)
static constexpr int NSTAGE = 4;
static constexpr int SMEM_BYTES = NSTAGE * STAGE_B; // 163840 B
static constexpr int PT = 136;                      // transpose staging pitch

// ============================================================================
// C[m0:+128, n0:+128] = sum_k A[m][k]*B[n][k]   (A,B K-major, hi/lo split)
// MODE 0: qkv (bias; epilogue -> q/k rows + vT transposed, all split h/l)
// MODE 1: scores (*scale -> fp32; causal/pad block skip)
// MODE 2: out (k range [np, m0+128); fp32 -> d_out)
// ============================================================================
template<int MODE>
__global__ __launch_bounds__(256) void hmma_gemm(
    const __nv_bfloat16* __restrict__ Ah, const __nv_bfloat16* __restrict__ Al, int lda,
    const __nv_bfloat16* __restrict__ Bh, const __nv_bfloat16* __restrict__ Bl, int ldb,
    int K, const float* __restrict__ bias, float scale,
    float* __restrict__ outf, int ldo,
    __nv_bfloat16* __restrict__ qh, __nv_bfloat16* __restrict__ ql,
    __nv_bfloat16* __restrict__ kh, __nv_bfloat16* __restrict__ kl,
    __nv_bfloat16* __restrict__ vTh, __nv_bfloat16* __restrict__ vTl,
    int F, int S, const int* __restrict__ np_ptr)
{
    const int m0 = blockIdx.y * 128;
    const int n0 = blockIdx.x * 128;
    const int np = *np_ptr;

    if (MODE == 0) { if (m0 + 128 <= np) return; }
    if (MODE == 1) {
        if (n0 > m0) return;
        if (m0 + 128 <= np) return;
        if (n0 + 128 <= np) return;
    }

    int c0 = 0, c1 = K >> 5;
    if (MODE == 2) { c0 = np >> 5; c1 = (m0 + 128) >> 5; }
    const int nchunks = c1 - c0;

    extern __shared__ __align__(128) char smem[];
    const uint32_t sbase = smem_u32(smem);

    const int tid  = threadIdx.x;
    const int wid  = tid >> 5;
    const int lane = tid & 31;
    const int wm   = (wid >> 2) * 64;
    const int wn   = (wid & 3) * 32;

    float acc[4][4][4];
    #pragma unroll
    for (int i = 0; i < 4; i++)
        #pragma unroll
        for (int j = 0; j < 4; j++)
            #pragma unroll
            for (int e = 0; e < 4; e++) acc[i][j][e] = 0.f;

    auto prefetch = [&](int c, int stage) {
        const int kc = c << 5;
        const uint32_t st = sbase + stage * STAGE_B;
        #pragma unroll
        for (int t = 0; t < 2; t++) {
            const int idx = tid + t * 256;
            const int r   = idx >> 2;
            const int seg = idx & 3;
            const uint32_t d = (uint32_t)(r * PA * 2 + seg * 16);
            CP_ASYNC16(st + 0 * TILE_B + d, &Ah[(size_t)(m0 + r) * lda + kc + seg * 8]);
            CP_ASYNC16(st + 1 * TILE_B + d, &Al[(size_t)(m0 + r) * lda + kc + seg * 8]);
            CP_ASYNC16(st + 2 * TILE_B + d, &Bh[(size_t)(n0 + r) * ldb + kc + seg * 8]);
            CP_ASYNC16(st + 3 * TILE_B + d, &Bl[(size_t)(n0 + r) * ldb + kc + seg * 8]);
        }
    };

    if (nchunks > 0) {
        // prologue: fill up to 3 stages
        #pragma unroll
        for (int s = 0; s < NSTAGE - 1; s++) {
            if (s < nchunks) prefetch(c0 + s, s);
            CP_COMMIT();
        }

        for (int i = 0; i < nchunks; i++) {
            CP_WAIT2();          // stage i resident
            __syncthreads();     // all warps past compute of stage i-1

            // prefetch stage i+3 into slot (i+3)%4 = (i-1)%4 (just-freed)
            if (i + NSTAGE - 1 < nchunks) prefetch(c0 + i + NSTAGE - 1, (i + NSTAGE - 1) & 3);
            CP_COMMIT();

            const uint32_t st = sbase + (i & 3) * STAGE_B;
            const uint32_t aH = st + 0 * TILE_B, aL = st + 1 * TILE_B;
            const uint32_t bH = st + 2 * TILE_B, bL = st + 3 * TILE_B;

            #pragma unroll
            for (int ks = 0; ks < 2; ks++) {
                const int k0 = ks * 16;
                uint32_t bh[4][2], bl[4][2];
                const int brow = wn + (lane & 7);
                const int bcol = k0 + ((lane >> 3) & 1) * 8;
                #pragma unroll
                for (int nt = 0; nt < 4; nt++) {
                    const uint32_t off = (uint32_t)(((brow + nt * 8) * PA + bcol) * 2);
                    ldsm_x2(bh[nt], bH + off);
                    ldsm_x2(bl[nt], bL + off);
                }
                const int arow = wm + (lane & 15);
                const int acol = k0 + (lane >> 4) * 8;
                #pragma unroll
                for (int mt = 0; mt < 4; mt++) {
                    const uint32_t off = (uint32_t)(((arow + mt * 16) * PA + acol) * 2);
                    uint32_t a[4];
                    ldsm_x4(a, aH + off);
                    #pragma unroll
                    for (int nt = 0; nt < 4; nt++) mma16816(acc[mt][nt], a, bh[nt]);
                    #pragma unroll
                    for (int nt = 0; nt < 4; nt++) mma16816(acc[mt][nt], a, bl[nt]);
                    ldsm_x4(a, aL + off);
                    #pragma unroll
                    for (int nt = 0; nt < 4; nt++) mma16816(acc[mt][nt], a, bh[nt]);
                }
            }
        }
    }

    // ---------------- epilogue ----------------------------------------------
    const int mq = lane >> 2;
    const int nq = (lane & 3) * 2;

    if (MODE == 0) {
        const int region = n0 / F;      // 0=q 1=k 2=v
        if (region < 2) {
            __nv_bfloat16* Dh = region ? kh : qh;
            __nv_bfloat16* Dl = region ? kl : ql;
            const int nb = n0 - region * F;
            #pragma unroll
            for (int mt = 0; mt < 4; mt++) {
                const int r0 = m0 + wm + mt * 16 + mq;
                #pragma unroll
                for (int nt = 0; nt < 4; nt++) {
                    const int nl = nb + wn + nt * 8 + nq;
                    const int gn = n0 + wn + nt * 8 + nq;
                    float v0 = acc[mt][nt][0] + bias[gn];
                    float v1 = acc[mt][nt][1] + bias[gn + 1];
                    float v2 = acc[mt][nt][2] + bias[gn];
                    float v3 = acc[mt][nt][3] + bias[gn + 1];
                    __nv_bfloat16 h0, l0, h1, l1;
                    split_bf16(v0, h0, l0); split_bf16(v1, h1, l1);
                    *(__nv_bfloat162*)&Dh[(size_t)r0 * F + nl] = __nv_bfloat162(h0, h1);
                    *(__nv_bfloat162*)&Dl[(size_t)r0 * F + nl] = __nv_bfloat162(l0, l1);
                    split_bf16(v2, h0, l0); split_bf16(v3, h1, l1);
                    *(__nv_bfloat162*)&Dh[(size_t)(r0 + 8) * F + nl] = __nv_bfloat162(h0, h1);
                    *(__nv_bfloat162*)&Dl[(size_t)(r0 + 8) * F + nl] = __nv_bfloat162(l0, l1);
                }
            }
        } else {
            // v region: stage transposed tile in smem, write vT coalesced
            CP_WAIT0();
            __nv_bfloat16* smem_t = (__nv_bfloat16*)smem;
            const int vb = n0 - 2 * F;
            #pragma unroll
            for (int pass = 0; pass < 2; pass++) {
                __syncthreads();
                #pragma unroll
                for (int mt = 0; mt < 4; mt++) {
                    const int ml = wm + mt * 16 + mq;
                    #pragma unroll
                    for (int nt = 0; nt < 4; nt++) {
                        const int nl = wn + nt * 8 + nq;
                        const int gn = n0 + wn + nt * 8 + nq;
                        #pragma unroll
                        for (int e = 0; e < 4; e++) {
                            const int nn = nl + (e & 1);
                            const int mm = ml + (e >> 1) * 8;
                            float v = acc[mt][nt][e] + bias[gn + (e & 1)];
                            __nv_bfloat16 h = __float2bfloat16(v);
                            __nv_bfloat16 o = h;
                            if (pass) o = __float2bfloat16(v - __bfloat162float(h));
                            smem_t[nn * PT + mm] = o;
                        }
                    }
                }
                __syncthreads();
                __nv_bfloat16* D = pass ? vTl : vTh;
                const int r = tid >> 1;
                const int sg = (tid & 1) * 64;
                const uint4* src = (const uint4*)&smem_t[r * PT + sg];
                uint4* dst = (uint4*)&D[(size_t)(vb + r) * S + m0 + sg];
                #pragma unroll
                for (int j = 0; j < 8; j++) dst[j] = src[j];
            }
        }
    } else {
        #pragma unroll
        for (int mt = 0; mt < 4; mt++) {
            const int r0 = m0 + wm + mt * 16 + mq;
            #pragma unroll
            for (int nt = 0; nt < 4; nt++) {
                const int gn = n0 + wn + nt * 8 + nq;
                float2 p0, p1;
                p0.x = acc[mt][nt][0] * scale;  p0.y = acc[mt][nt][1] * scale;
                p1.x = acc[mt][nt][2] * scale;  p1.y = acc[mt][nt][3] * scale;
                *(float2*)&outf[(size_t)r0 * ldo + gn]       = p0;
                *(float2*)&outf[(size_t)(r0 + 8) * ldo + gn] = p1;
            }
        }
    }
}

// ---------------- fp32 -> bf16 hi/lo elementwise ----------------------------
__global__ __launch_bounds__(256) void split_convert_kernel(
    const float* __restrict__ in, __nv_bfloat16* __restrict__ h,
    __nv_bfloat16* __restrict__ l, size_t n4)
{
    for (size_t i = blockIdx.x * 256 + threadIdx.x; i < n4; i += (size_t)gridDim.x * 256) {
        float4 v = ((const float4*)in)[i];
        __nv_bfloat16 hh[4], ll[4];
        split_bf16(v.x, hh[0], ll[0]);
        split_bf16(v.y, hh[1], ll[1]);
        split_bf16(v.z, hh[2], ll[2]);
        split_bf16(v.w, hh[3], ll[3]);
        ((__nv_bfloat162*)h)[i * 2 + 0] = __nv_bfloat162(hh[0], hh[1]);
        ((__nv_bfloat162*)h)[i * 2 + 1] = __nv_bfloat162(hh[2], hh[3]);
        ((__nv_bfloat162*)l)[i * 2 + 0] = __nv_bfloat162(ll[0], ll[1]);
        ((__nv_bfloat162*)l)[i * 2 + 1] = __nv_bfloat162(ll[2], ll[3]);
    }
}

// ---------------- transpose + split: Wt[c][r] = W[r][c] ---------------------
__global__ __launch_bounds__(256) void transpose_split_kernel(
    const float* __restrict__ W, __nv_bfloat16* __restrict__ Th,
    __nv_bfloat16* __restrict__ Tl, int rows, int cols)
{
    __shared__ float tile[32][33];
    const int bx = blockIdx.x * 32;
    const int by = blockIdx.y * 32;
    const int tx = threadIdx.x & 31;
    const int ty = threadIdx.x >> 5;
    #pragma unroll
    for (int i = 0; i < 4; i++)
        tile[ty + i * 8][tx] = W[(size_t)(by + ty + i * 8) * cols + bx + tx];
    __syncthreads();
    #pragma unroll
    for (int i = 0; i < 4; i++) {
        const int orow = bx + ty + i * 8;
        const int ocol = by + tx;
        __nv_bfloat16 h, l;
        split_bf16(tile[tx][ty + i * 8], h, l);
        Th[(size_t)orow * rows + ocol] = h;
        Tl[(size_t)orow * rows + ocol] = l;
    }
}

// ---------------- softmax: fp32 scores -> att bf16 hi/lo --------------------
__global__ __launch_bounds__(256) void softmax_kernel(
    float* __restrict__ s, __nv_bfloat16* __restrict__ ah,
    __nv_bfloat16* __restrict__ al, int S, const int* __restrict__ np_ptr)
{
    const int i = blockIdx.x;
    const int np = *np_ptr;
    float* row = s + (size_t)i * S;
    __nv_bfloat16* rh = ah + (size_t)i * S;
    __nv_bfloat16* rl = al + (size_t)i * S;
    const int tid = threadIdx.x;
    __shared__ float red[256];

    if (i < np) {
        const __nv_bfloat16 z = __float2bfloat16(0.f);
        for (int j = tid; j < S; j += 256) { rh[j] = z; rl[j] = z; }
        return;
    }
    float m = -3.402823e38f;
    for (int j = np + tid; j <= i; j += 256) m = fmaxf(m, row[j]);
    red[tid] = m; __syncthreads();
    for (int off = 128; off > 0; off >>= 1) {
        if (tid < off) red[tid] = fmaxf(red[tid], red[tid + off]);
        __syncthreads();
    }
    m = red[0]; __syncthreads();

    float sum = 0.f;
    for (int j = np + tid; j <= i; j += 256) {
        float e = __expf(row[j] - m);
        row[j] = e;
        sum += e;
    }
    red[tid] = sum; __syncthreads();
    for (int off = 128; off > 0; off >>= 1) {
        if (tid < off) red[tid] += red[tid + off];
        __syncthreads();
    }
    const float inv = 1.f / red[0]; __syncthreads();

    for (int j = tid; j < S; j += 256) {
        float p = (j >= np && j <= i) ? row[j] * inv : 0.f;
        __nv_bfloat16 h, l;
        split_bf16(p, h, l);
        rh[j] = h; rl[j] = l;
    }
}

// ============================================================================
extern "C" void kernel_launch(void* const* d_in, const int* in_sizes, int n_in,
                              void* d_out, int out_size)
{
    const float* x  = (const float*)d_in[0];
    const float* W  = (const float*)d_in[1];
    const float* b  = (const float*)d_in[2];
    const int*   np = (const int*)  d_in[3];

    const int F3 = in_sizes[2];      // 6144
    const int F  = F3 / 3;           // 2048
    const int S  = in_sizes[0] / F;  // 4096
    float* out = (float*)d_out;

    __nv_bfloat16 *xh, *xl, *Wth, *Wtl, *qh, *ql, *kh, *kl, *vTh, *vTl, *atth, *attl;
    float* sc;
    cudaGetSymbolAddress((void**)&xh,  g_xh);   cudaGetSymbolAddress((void**)&xl,  g_xl);
    cudaGetSymbolAddress((void**)&Wth, g_Wth);  cudaGetSymbolAddress((void**)&Wtl, g_Wtl);
    cudaGetSymbolAddress((void**)&qh,  g_qh);   cudaGetSymbolAddress((void**)&ql,  g_ql);
    cudaGetSymbolAddress((void**)&kh,  g_kh);   cudaGetSymbolAddress((void**)&kl,  g_kl);
    cudaGetSymbolAddress((void**)&vTh, g_vTh);  cudaGetSymbolAddress((void**)&vTl, g_vTl);
    cudaGetSymbolAddress((void**)&sc,  g_scores);
    cudaGetSymbolAddress((void**)&atth, g_atth); cudaGetSymbolAddress((void**)&attl, g_attl);

    cudaFuncSetAttribute(hmma_gemm<0>, cudaFuncAttributeMaxDynamicSharedMemorySize, SMEM_BYTES);
    cudaFuncSetAttribute(hmma_gemm<1>, cudaFuncAttributeMaxDynamicSharedMemorySize, SMEM_BYTES);
    cudaFuncSetAttribute(hmma_gemm<2>, cudaFuncAttributeMaxDynamicSharedMemorySize, SMEM_BYTES);

    const float scale = 1.0f / sqrtf((float)F);

    split_convert_kernel<<<4096, 256>>>(x, xh, xl, (size_t)S * F / 4);
    transpose_split_kernel<<<dim3(F3 / 32, F / 32), 256>>>(W, Wth, Wtl, F, F3);

    hmma_gemm<0><<<dim3(F3 / 128, S / 128), 256, SMEM_BYTES>>>(
        xh, xl, F, Wth, Wtl, F, F, b, 1.0f, nullptr, 0,
        qh, ql, kh, kl, vTh, vTl, F, S, np);

    hmma_gemm<1><<<dim3(S / 128, S / 128), 256, SMEM_BYTES>>>(
        qh, ql, F, kh, kl, F, F, nullptr, scale, sc, S,
        nullptr, nullptr, nullptr, nullptr, nullptr, nullptr, F, S, np);

    softmax_kernel<<<S, 256>>>(sc, atth, attl, S, np);

    hmma_gemm<2><<<dim3(F / 128, S / 128), 256, SMEM_BYTES>>>(
        atth, attl, S, vTh, vTl, S, S, nullptr, 1.0f, out, F,
        nullptr, nullptr, nullptr, nullptr, nullptr, nullptr, F, S, np);
}

// round 5
// speedup vs baseline: 1.1207x; 1.1207x over previous
#include <cuda_runtime.h>
#include <cuda_bf16.h>
#include <math.h>
#include <stdint.h>

// ============================================================================
// PaddedSHCSA via mma.sync bf16 split hi/lo 3-pass. Round 5: 2 CTAs/SM
// (2-stage smem = 80KB, __launch_bounds__(256,2) -> 128 regs) to double
// warps/SMSP and raise tensor-pipe duty cycle.
// ============================================================================

#define S_DIM   4096
#define F_DIM   2048
#define F3_DIM  6144

__device__ __nv_bfloat16 g_xh [(size_t)S_DIM * F_DIM];
__device__ __nv_bfloat16 g_xl [(size_t)S_DIM * F_DIM];
__device__ __nv_bfloat16 g_Wth[(size_t)F3_DIM * F_DIM];   // W^T [3F][F]
__device__ __nv_bfloat16 g_Wtl[(size_t)F3_DIM * F_DIM];
__device__ __nv_bfloat16 g_qh [(size_t)S_DIM * F_DIM];
__device__ __nv_bfloat16 g_ql [(size_t)S_DIM * F_DIM];
__device__ __nv_bfloat16 g_kh [(size_t)S_DIM * F_DIM];
__device__ __nv_bfloat16 g_kl [(size_t)S_DIM * F_DIM];
__device__ __nv_bfloat16 g_vTh[(size_t)F_DIM * S_DIM];    // v^T [F][S]
__device__ __nv_bfloat16 g_vTl[(size_t)F_DIM * S_DIM];
__device__ float         g_scores[(size_t)S_DIM * S_DIM];
__device__ __nv_bfloat16 g_atth[(size_t)S_DIM * S_DIM];
__device__ __nv_bfloat16 g_attl[(size_t)S_DIM * S_DIM];

// ---------------- low-level helpers -----------------------------------------
__device__ __forceinline__ uint32_t smem_u32(const void* p) {
    uint32_t a;
    asm("{ .reg .u64 t; cvta.to.shared.u64 t, %1; cvt.u32.u64 %0, t; }" : "=r"(a) : "l"(p));
    return a;
}
#define CP_ASYNC16(dst_u32, src_ptr) \
    asm volatile("cp.async.cg.shared.global [%0], [%1], 16;" :: "r"(dst_u32), "l"(src_ptr))
#define CP_COMMIT()  asm volatile("cp.async.commit_group;" ::: "memory")
#define CP_WAIT1()   asm volatile("cp.async.wait_group 1;" ::: "memory")
#define CP_WAIT0()   asm volatile("cp.async.wait_group 0;" ::: "memory")

__device__ __forceinline__ void ldsm_x4(uint32_t* r, uint32_t addr) {
    asm volatile("ldmatrix.sync.aligned.m8n8.x4.shared.b16 {%0,%1,%2,%3}, [%4];"
        : "=r"(r[0]), "=r"(r[1]), "=r"(r[2]), "=r"(r[3]) : "r"(addr));
}
__device__ __forceinline__ void ldsm_x2(uint32_t* r, uint32_t addr) {
    asm volatile("ldmatrix.sync.aligned.m8n8.x2.shared.b16 {%0,%1}, [%2];"
        : "=r"(r[0]), "=r"(r[1]) : "r"(addr));
}
__device__ __forceinline__ void mma16816(float* c, const uint32_t* a, const uint32_t* b) {
    asm volatile("mma.sync.aligned.m16n8k16.row.col.f32.bf16.bf16.f32 "
        "{%0,%1,%2,%3}, {%4,%5,%6,%7}, {%8,%9}, {%0,%1,%2,%3};"
        : "+f"(c[0]), "+f"(c[1]), "+f"(c[2]), "+f"(c[3])
        : "r"(a[0]), "r"(a[1]), "r"(a[2]), "r"(a[3]), "r"(b[0]), "r"(b[1]));
}
__device__ __forceinline__ void split_bf16(float v, __nv_bfloat16& h, __nv_bfloat16& l) {
    h = __float2bfloat16(v);
    l = __float2bfloat16(v - __bfloat162float(h));
}

// ---------------- smem layout -----------------------------------------------
static constexpr int PA = 40;                       // pitch in halves
static constexpr int TILE_B = 128 * PA * 2;         // 10240 B
static constexpr int STAGE_B = 4 * TILE_B;          // 40960 B (Ah Al Bh Bl)
static constexpr int SMEM_BYTES = 2 * STAGE_B;      // 81920 B -> 2 CTAs/SM
static constexpr int PT = 136;                      // transpose staging pitch

// ============================================================================
// C[m0:+128, n0:+128] = sum_k A[m][k]*B[n][k]   (A,B K-major, hi/lo split)
// MODE 0: qkv (bias; epilogue -> q/k rows + vT transposed, all split h/l)
// MODE 1: scores (*scale -> fp32; causal/pad block skip)
// MODE 2: out (k range [np, m0+128); fp32 -> d_out)
// ============================================================================
template<int MODE>
__global__ __launch_bounds__(256, 2) void hmma_gemm(
    const __nv_bfloat16* __restrict__ Ah, const __nv_bfloat16* __restrict__ Al, int lda,
    const __nv_bfloat16* __restrict__ Bh, const __nv_bfloat16* __restrict__ Bl, int ldb,
    int K, const float* __restrict__ bias, float scale,
    float* __restrict__ outf, int ldo,
    __nv_bfloat16* __restrict__ qh, __nv_bfloat16* __restrict__ ql,
    __nv_bfloat16* __restrict__ kh, __nv_bfloat16* __restrict__ kl,
    __nv_bfloat16* __restrict__ vTh, __nv_bfloat16* __restrict__ vTl,
    int F, int S, const int* __restrict__ np_ptr)
{
    const int m0 = blockIdx.y * 128;
    const int n0 = blockIdx.x * 128;
    const int np = *np_ptr;

    if (MODE == 0) { if (m0 + 128 <= np) return; }
    if (MODE == 1) {
        if (n0 > m0) return;
        if (m0 + 128 <= np) return;
        if (n0 + 128 <= np) return;
    }

    int c0 = 0, c1 = K >> 5;
    if (MODE == 2) { c0 = np >> 5; c1 = (m0 + 128) >> 5; }
    const int nchunks = c1 - c0;

    extern __shared__ __align__(128) char smem[];
    const uint32_t sbase = smem_u32(smem);

    const int tid  = threadIdx.x;
    const int wid  = tid >> 5;
    const int lane = tid & 31;
    const int wm   = (wid >> 2) * 64;
    const int wn   = (wid & 3) * 32;

    float acc[4][4][4];
    #pragma unroll
    for (int i = 0; i < 4; i++)
        #pragma unroll
        for (int j = 0; j < 4; j++)
            #pragma unroll
            for (int e = 0; e < 4; e++) acc[i][j][e] = 0.f;

    auto prefetch = [&](int c, int stage) {
        const int kc = c << 5;
        const uint32_t st = sbase + stage * STAGE_B;
        #pragma unroll
        for (int t = 0; t < 2; t++) {
            const int idx = tid + t * 256;
            const int r   = idx >> 2;
            const int seg = idx & 3;
            const uint32_t d = (uint32_t)(r * PA * 2 + seg * 16);
            CP_ASYNC16(st + 0 * TILE_B + d, &Ah[(size_t)(m0 + r) * lda + kc + seg * 8]);
            CP_ASYNC16(st + 1 * TILE_B + d, &Al[(size_t)(m0 + r) * lda + kc + seg * 8]);
            CP_ASYNC16(st + 2 * TILE_B + d, &Bh[(size_t)(n0 + r) * ldb + kc + seg * 8]);
            CP_ASYNC16(st + 3 * TILE_B + d, &Bl[(size_t)(n0 + r) * ldb + kc + seg * 8]);
        }
    };

    if (nchunks > 0) {
        prefetch(c0, 0); CP_COMMIT();
        if (nchunks > 1) prefetch(c0 + 1, 1);
        CP_COMMIT();

        for (int i = 0; i < nchunks; i++) {
            CP_WAIT1();
            __syncthreads();
            const uint32_t st = sbase + (i & 1) * STAGE_B;
            const uint32_t aH = st + 0 * TILE_B, aL = st + 1 * TILE_B;
            const uint32_t bH = st + 2 * TILE_B, bL = st + 3 * TILE_B;

            #pragma unroll
            for (int ks = 0; ks < 2; ks++) {
                const int k0 = ks * 16;
                uint32_t bh[4][2], bl[4][2];
                const int brow = wn + (lane & 7);
                const int bcol = k0 + ((lane >> 3) & 1) * 8;
                #pragma unroll
                for (int nt = 0; nt < 4; nt++) {
                    const uint32_t off = (uint32_t)(((brow + nt * 8) * PA + bcol) * 2);
                    ldsm_x2(bh[nt], bH + off);
                    ldsm_x2(bl[nt], bL + off);
                }
                const int arow = wm + (lane & 15);
                const int acol = k0 + (lane >> 4) * 8;
                #pragma unroll
                for (int mt = 0; mt < 4; mt++) {
                    const uint32_t off = (uint32_t)(((arow + mt * 16) * PA + acol) * 2);
                    uint32_t a[4];
                    ldsm_x4(a, aH + off);
                    #pragma unroll
                    for (int nt = 0; nt < 4; nt++) mma16816(acc[mt][nt], a, bh[nt]);
                    #pragma unroll
                    for (int nt = 0; nt < 4; nt++) mma16816(acc[mt][nt], a, bl[nt]);
                    ldsm_x4(a, aL + off);
                    #pragma unroll
                    for (int nt = 0; nt < 4; nt++) mma16816(acc[mt][nt], a, bh[nt]);
                }
            }
            __syncthreads();
            if (i + 2 < nchunks) prefetch(c0 + i + 2, i & 1);
            CP_COMMIT();
        }
    }

    // ---------------- epilogue ----------------------------------------------
    const int mq = lane >> 2;
    const int nq = (lane & 3) * 2;

    if (MODE == 0) {
        const int region = n0 / F;      // 0=q 1=k 2=v
        if (region < 2) {
            __nv_bfloat16* Dh = region ? kh : qh;
            __nv_bfloat16* Dl = region ? kl : ql;
            const int nb = n0 - region * F;
            #pragma unroll
            for (int mt = 0; mt < 4; mt++) {
                const int r0 = m0 + wm + mt * 16 + mq;
                #pragma unroll
                for (int nt = 0; nt < 4; nt++) {
                    const int nl = nb + wn + nt * 8 + nq;
                    const int gn = n0 + wn + nt * 8 + nq;
                    float v0 = acc[mt][nt][0] + bias[gn];
                    float v1 = acc[mt][nt][1] + bias[gn + 1];
                    float v2 = acc[mt][nt][2] + bias[gn];
                    float v3 = acc[mt][nt][3] + bias[gn + 1];
                    __nv_bfloat16 h0, l0, h1, l1;
                    split_bf16(v0, h0, l0); split_bf16(v1, h1, l1);
                    *(__nv_bfloat162*)&Dh[(size_t)r0 * F + nl] = __nv_bfloat162(h0, h1);
                    *(__nv_bfloat162*)&Dl[(size_t)r0 * F + nl] = __nv_bfloat162(l0, l1);
                    split_bf16(v2, h0, l0); split_bf16(v3, h1, l1);
                    *(__nv_bfloat162*)&Dh[(size_t)(r0 + 8) * F + nl] = __nv_bfloat162(h0, h1);
                    *(__nv_bfloat162*)&Dl[(size_t)(r0 + 8) * F + nl] = __nv_bfloat162(l0, l1);
                }
            }
        } else {
            // v region: stage transposed tile in smem, write vT coalesced
            CP_WAIT0();
            __nv_bfloat16* smem_t = (__nv_bfloat16*)smem;
            const int vb = n0 - 2 * F;
            #pragma unroll
            for (int pass = 0; pass < 2; pass++) {
                __syncthreads();
                #pragma unroll
                for (int mt = 0; mt < 4; mt++) {
                    const int ml = wm + mt * 16 + mq;
                    #pragma unroll
                    for (int nt = 0; nt < 4; nt++) {
                        const int nl = wn + nt * 8 + nq;
                        const int gn = n0 + wn + nt * 8 + nq;
                        #pragma unroll
                        for (int e = 0; e < 4; e++) {
                            const int nn = nl + (e & 1);
                            const int mm = ml + (e >> 1) * 8;
                            float v = acc[mt][nt][e] + bias[gn + (e & 1)];
                            __nv_bfloat16 h = __float2bfloat16(v);
                            __nv_bfloat16 o = h;
                            if (pass) o = __float2bfloat16(v - __bfloat162float(h));
                            smem_t[nn * PT + mm] = o;
                        }
                    }
                }
                __syncthreads();
                __nv_bfloat16* D = pass ? vTl : vTh;
                const int r = tid >> 1;
                const int sg = (tid & 1) * 64;
                const uint4* src = (const uint4*)&smem_t[r * PT + sg];
                uint4* dst = (uint4*)&D[(size_t)(vb + r) * S + m0 + sg];
                #pragma unroll
                for (int j = 0; j < 8; j++) dst[j] = src[j];
            }
        }
    } else {
        #pragma unroll
        for (int mt = 0; mt < 4; mt++) {
            const int r0 = m0 + wm + mt * 16 + mq;
            #pragma unroll
            for (int nt = 0; nt < 4; nt++) {
                const int gn = n0 + wn + nt * 8 + nq;
                float2 p0, p1;
                p0.x = acc[mt][nt][0] * scale;  p0.y = acc[mt][nt][1] * scale;
                p1.x = acc[mt][nt][2] * scale;  p1.y = acc[mt][nt][3] * scale;
                *(float2*)&outf[(size_t)r0 * ldo + gn]       = p0;
                *(float2*)&outf[(size_t)(r0 + 8) * ldo + gn] = p1;
            }
        }
    }
}

// ---------------- fp32 -> bf16 hi/lo elementwise ----------------------------
__global__ __launch_bounds__(256) void split_convert_kernel(
    const float* __restrict__ in, __nv_bfloat16* __restrict__ h,
    __nv_bfloat16* __restrict__ l, size_t n4)
{
    for (size_t i = blockIdx.x * 256 + threadIdx.x; i < n4; i += (size_t)gridDim.x * 256) {
        float4 v = ((const float4*)in)[i];
        __nv_bfloat16 hh[4], ll[4];
        split_bf16(v.x, hh[0], ll[0]);
        split_bf16(v.y, hh[1], ll[1]);
        split_bf16(v.z, hh[2], ll[2]);
        split_bf16(v.w, hh[3], ll[3]);
        ((__nv_bfloat162*)h)[i * 2 + 0] = __nv_bfloat162(hh[0], hh[1]);
        ((__nv_bfloat162*)h)[i * 2 + 1] = __nv_bfloat162(hh[2], hh[3]);
        ((__nv_bfloat162*)l)[i * 2 + 0] = __nv_bfloat162(ll[0], ll[1]);
        ((__nv_bfloat162*)l)[i * 2 + 1] = __nv_bfloat162(ll[2], ll[3]);
    }
}

// ---------------- transpose + split: Wt[c][r] = W[r][c] ---------------------
__global__ __launch_bounds__(256) void transpose_split_kernel(
    const float* __restrict__ W, __nv_bfloat16* __restrict__ Th,
    __nv_bfloat16* __restrict__ Tl, int rows, int cols)
{
    __shared__ float tile[32][33];
    const int bx = blockIdx.x * 32;
    const int by = blockIdx.y * 32;
    const int tx = threadIdx.x & 31;
    const int ty = threadIdx.x >> 5;
    #pragma unroll
    for (int i = 0; i < 4; i++)
        tile[ty + i * 8][tx] = W[(size_t)(by + ty + i * 8) * cols + bx + tx];
    __syncthreads();
    #pragma unroll
    for (int i = 0; i < 4; i++) {
        const int orow = bx + ty + i * 8;
        const int ocol = by + tx;
        __nv_bfloat16 h, l;
        split_bf16(tile[tx][ty + i * 8], h, l);
        Th[(size_t)orow * rows + ocol] = h;
        Tl[(size_t)orow * rows + ocol] = l;
    }
}

// ---------------- softmax: fp32 scores -> att bf16 hi/lo --------------------
__global__ __launch_bounds__(256) void softmax_kernel(
    float* __restrict__ s, __nv_bfloat16* __restrict__ ah,
    __nv_bfloat16* __restrict__ al, int S, const int* __restrict__ np_ptr)
{
    const int i = blockIdx.x;
    const int np = *np_ptr;
    float* row = s + (size_t)i * S;
    __nv_bfloat16* rh = ah + (size_t)i * S;
    __nv_bfloat16* rl = al + (size_t)i * S;
    const int tid = threadIdx.x;
    __shared__ float red[256];

    if (i < np) {
        const __nv_bfloat16 z = __float2bfloat16(0.f);
        for (int j = tid; j < S; j += 256) { rh[j] = z; rl[j] = z; }
        return;
    }
    float m = -3.402823e38f;
    for (int j = np + tid; j <= i; j += 256) m = fmaxf(m, row[j]);
    red[tid] = m; __syncthreads();
    for (int off = 128; off > 0; off >>= 1) {
        if (tid < off) red[tid] = fmaxf(red[tid], red[tid + off]);
        __syncthreads();
    }
    m = red[0]; __syncthreads();

    float sum = 0.f;
    for (int j = np + tid; j <= i; j += 256) {
        float e = __expf(row[j] - m);
        row[j] = e;
        sum += e;
    }
    red[tid] = sum; __syncthreads();
    for (int off = 128; off > 0; off >>= 1) {
        if (tid < off) red[tid] += red[tid + off];
        __syncthreads();
    }
    const float inv = 1.f / red[0]; __syncthreads();

    for (int j = tid; j < S; j += 256) {
        float p = (j >= np && j <= i) ? row[j] * inv : 0.f;
        __nv_bfloat16 h, l;
        split_bf16(p, h, l);
        rh[j] = h; rl[j] = l;
    }
}

// ============================================================================
extern "C" void kernel_launch(void* const* d_in, const int* in_sizes, int n_in,
                              void* d_out, int out_size)
{
    const float* x  = (const float*)d_in[0];
    const float* W  = (const float*)d_in[1];
    const float* b  = (const float*)d_in[2];
    const int*   np = (const int*)  d_in[3];

    const int F3 = in_sizes[2];      // 6144
    const int F  = F3 / 3;           // 2048
    const int S  = in_sizes[0] / F;  // 4096
    float* out = (float*)d_out;

    __nv_bfloat16 *xh, *xl, *Wth, *Wtl, *qh, *ql, *kh, *kl, *vTh, *vTl, *atth, *attl;
    float* sc;
    cudaGetSymbolAddress((void**)&xh,  g_xh);   cudaGetSymbolAddress((void**)&xl,  g_xl);
    cudaGetSymbolAddress((void**)&Wth, g_Wth);  cudaGetSymbolAddress((void**)&Wtl, g_Wtl);
    cudaGetSymbolAddress((void**)&qh,  g_qh);   cudaGetSymbolAddress((void**)&ql,  g_ql);
    cudaGetSymbolAddress((void**)&kh,  g_kh);   cudaGetSymbolAddress((void**)&kl,  g_kl);
    cudaGetSymbolAddress((void**)&vTh, g_vTh);  cudaGetSymbolAddress((void**)&vTl, g_vTl);
    cudaGetSymbolAddress((void**)&sc,  g_scores);
    cudaGetSymbolAddress((void**)&atth, g_atth); cudaGetSymbolAddress((void**)&attl, g_attl);

    cudaFuncSetAttribute(hmma_gemm<0>, cudaFuncAttributeMaxDynamicSharedMemorySize, SMEM_BYTES);
    cudaFuncSetAttribute(hmma_gemm<1>, cudaFuncAttributeMaxDynamicSharedMemorySize, SMEM_BYTES);
    cudaFuncSetAttribute(hmma_gemm<2>, cudaFuncAttributeMaxDynamicSharedMemorySize, SMEM_BYTES);

    const float scale = 1.0f / sqrtf((float)F);

    split_convert_kernel<<<4096, 256>>>(x, xh, xl, (size_t)S * F / 4);
    transpose_split_kernel<<<dim3(F3 / 32, F / 32), 256>>>(W, Wth, Wtl, F, F3);

    hmma_gemm<0><<<dim3(F3 / 128, S / 128), 256, SMEM_BYTES>>>(
        xh, xl, F, Wth, Wtl, F, F, b, 1.0f, nullptr, 0,
        qh, ql, kh, kl, vTh, vTl, F, S, np);

    hmma_gemm<1><<<dim3(S / 128, S / 128), 256, SMEM_BYTES>>>(
        qh, ql, F, kh, kl, F, F, nullptr, scale, sc, S,
        nullptr, nullptr, nullptr, nullptr, nullptr, nullptr, F, S, np);

    softmax_kernel<<<S, 256>>>(sc, atth, attl, S, np);

    hmma_gemm<2><<<dim3(F / 128, S / 128), 256, SMEM_BYTES>>>(
        atth, attl, S, vTh, vTl, S, S, nullptr, 1.0f, out, F,
        nullptr, nullptr, nullptr, nullptr, nullptr, nullptr, F, S, np);
}

// round 6
// speedup vs baseline: 1.1535x; 1.0293x over previous
#include <cuda_runtime.h>
#include <cuda_bf16.h>
#include <math.h>
#include <stdint.h>

// ============================================================================
// PaddedSHCSA via mma.sync bf16 split hi/lo 3-pass. Round 6: pass-level
// software pipelining of ldmatrix (cover RAW latency with independent MMAs),
// B-frags via ldsm_x4 (2 n-tiles/instr). 2 CTAs/SM kept (<=128 regs).
// ============================================================================

#define S_DIM   4096
#define F_DIM   2048
#define F3_DIM  6144

__device__ __nv_bfloat16 g_xh [(size_t)S_DIM * F_DIM];
__device__ __nv_bfloat16 g_xl [(size_t)S_DIM * F_DIM];
__device__ __nv_bfloat16 g_Wth[(size_t)F3_DIM * F_DIM];   // W^T [3F][F]
__device__ __nv_bfloat16 g_Wtl[(size_t)F3_DIM * F_DIM];
__device__ __nv_bfloat16 g_qh [(size_t)S_DIM * F_DIM];
__device__ __nv_bfloat16 g_ql [(size_t)S_DIM * F_DIM];
__device__ __nv_bfloat16 g_kh [(size_t)S_DIM * F_DIM];
__device__ __nv_bfloat16 g_kl [(size_t)S_DIM * F_DIM];
__device__ __nv_bfloat16 g_vTh[(size_t)F_DIM * S_DIM];    // v^T [F][S]
__device__ __nv_bfloat16 g_vTl[(size_t)F_DIM * S_DIM];
__device__ float         g_scores[(size_t)S_DIM * S_DIM];
__device__ __nv_bfloat16 g_atth[(size_t)S_DIM * S_DIM];
__device__ __nv_bfloat16 g_attl[(size_t)S_DIM * S_DIM];

// ---------------- low-level helpers -----------------------------------------
__device__ __forceinline__ uint32_t smem_u32(const void* p) {
    uint32_t a;
    asm("{ .reg .u64 t; cvta.to.shared.u64 t, %1; cvt.u32.u64 %0, t; }" : "=r"(a) : "l"(p));
    return a;
}
#define CP_ASYNC16(dst_u32, src_ptr) \
    asm volatile("cp.async.cg.shared.global [%0], [%1], 16;" :: "r"(dst_u32), "l"(src_ptr))
#define CP_COMMIT()  asm volatile("cp.async.commit_group;" ::: "memory")
#define CP_WAIT1()   asm volatile("cp.async.wait_group 1;" ::: "memory")
#define CP_WAIT0()   asm volatile("cp.async.wait_group 0;" ::: "memory")

__device__ __forceinline__ void ldsm_x4(uint32_t* r, uint32_t addr) {
    asm volatile("ldmatrix.sync.aligned.m8n8.x4.shared.b16 {%0,%1,%2,%3}, [%4];"
        : "=r"(r[0]), "=r"(r[1]), "=r"(r[2]), "=r"(r[3]) : "r"(addr));
}
__device__ __forceinline__ void mma16816(float* c, const uint32_t* a, const uint32_t* b) {
    asm volatile("mma.sync.aligned.m16n8k16.row.col.f32.bf16.bf16.f32 "
        "{%0,%1,%2,%3}, {%4,%5,%6,%7}, {%8,%9}, {%0,%1,%2,%3};"
        : "+f"(c[0]), "+f"(c[1]), "+f"(c[2]), "+f"(c[3])
        : "r"(a[0]), "r"(a[1]), "r"(a[2]), "r"(a[3]), "r"(b[0]), "r"(b[1]));
}
__device__ __forceinline__ void split_bf16(float v, __nv_bfloat16& h, __nv_bfloat16& l) {
    h = __float2bfloat16(v);
    l = __float2bfloat16(v - __bfloat162float(h));
}

// ---------------- smem layout -----------------------------------------------
static constexpr int PA = 40;                       // pitch in halves
static constexpr int TILE_B = 128 * PA * 2;         // 10240 B
static constexpr int STAGE_B = 4 * TILE_B;          // 40960 B (Ah Al Bh Bl)
static constexpr int SMEM_BYTES = 2 * STAGE_B;      // 81920 B -> 2 CTAs/SM
static constexpr int PT = 136;                      // transpose staging pitch

// ============================================================================
// C[m0:+128, n0:+128] = sum_k A[m][k]*B[n][k]   (A,B K-major, hi/lo split)
// MODE 0: qkv (bias; epilogue -> q/k rows + vT transposed, all split h/l)
// MODE 1: scores (*scale -> fp32; causal/pad block skip)
// MODE 2: out (k range [np, m0+128); fp32 -> d_out)
// ============================================================================
template<int MODE>
__global__ __launch_bounds__(256, 2) void hmma_gemm(
    const __nv_bfloat16* __restrict__ Ah, const __nv_bfloat16* __restrict__ Al, int lda,
    const __nv_bfloat16* __restrict__ Bh, const __nv_bfloat16* __restrict__ Bl, int ldb,
    int K, const float* __restrict__ bias, float scale,
    float* __restrict__ outf, int ldo,
    __nv_bfloat16* __restrict__ qh, __nv_bfloat16* __restrict__ ql,
    __nv_bfloat16* __restrict__ kh, __nv_bfloat16* __restrict__ kl,
    __nv_bfloat16* __restrict__ vTh, __nv_bfloat16* __restrict__ vTl,
    int F, int S, const int* __restrict__ np_ptr)
{
    const int m0 = blockIdx.y * 128;
    const int n0 = blockIdx.x * 128;
    const int np = *np_ptr;

    if (MODE == 0) { if (m0 + 128 <= np) return; }
    if (MODE == 1) {
        if (n0 > m0) return;
        if (m0 + 128 <= np) return;
        if (n0 + 128 <= np) return;
    }

    int c0 = 0, c1 = K >> 5;
    if (MODE == 2) { c0 = np >> 5; c1 = (m0 + 128) >> 5; }
    const int nchunks = c1 - c0;

    extern __shared__ __align__(128) char smem[];
    const uint32_t sbase = smem_u32(smem);

    const int tid  = threadIdx.x;
    const int wid  = tid >> 5;
    const int lane = tid & 31;
    const int wm   = (wid >> 2) * 64;
    const int wn   = (wid & 3) * 32;

    float acc[4][4][4];
    #pragma unroll
    for (int i = 0; i < 4; i++)
        #pragma unroll
        for (int j = 0; j < 4; j++)
            #pragma unroll
            for (int e = 0; e < 4; e++) acc[i][j][e] = 0.f;

    auto prefetch = [&](int c, int stage) {
        const int kc = c << 5;
        const uint32_t st = sbase + stage * STAGE_B;
        #pragma unroll
        for (int t = 0; t < 2; t++) {
            const int idx = tid + t * 256;
            const int r   = idx >> 2;
            const int seg = idx & 3;
            const uint32_t d = (uint32_t)(r * PA * 2 + seg * 16);
            CP_ASYNC16(st + 0 * TILE_B + d, &Ah[(size_t)(m0 + r) * lda + kc + seg * 8]);
            CP_ASYNC16(st + 1 * TILE_B + d, &Al[(size_t)(m0 + r) * lda + kc + seg * 8]);
            CP_ASYNC16(st + 2 * TILE_B + d, &Bh[(size_t)(n0 + r) * ldb + kc + seg * 8]);
            CP_ASYNC16(st + 3 * TILE_B + d, &Bl[(size_t)(n0 + r) * ldb + kc + seg * 8]);
        }
    };

    // per-lane ldmatrix address components (chunk-invariant)
    const int arow = wm + (lane & 15);             // A: rows for x4
    const int acolb = (lane >> 4) * 8;             // A: k sub-col
    const int brow = wn + (lane & 7) + ((lane >> 4) << 3);  // B: rows (+8 for T2/T3)
    const int bcolb = ((lane >> 3) & 1) << 3;      // B: k sub-col

    if (nchunks > 0) {
        prefetch(c0, 0); CP_COMMIT();
        if (nchunks > 1) prefetch(c0 + 1, 1);
        CP_COMMIT();

        for (int i = 0; i < nchunks; i++) {
            CP_WAIT1();
            __syncthreads();
            const uint32_t st = sbase + (i & 1) * STAGE_B;
            const uint32_t aHb = st + 0 * TILE_B, aLb = st + 1 * TILE_B;
            const uint32_t bHb = st + 2 * TILE_B, bLb = st + 3 * TILE_B;

            #pragma unroll
            for (int ks = 0; ks < 2; ks++) {
                const int k0 = ks * 16;
                uint32_t aH[2][4], aL[4];
                uint32_t bh[4][2], bl[4][2];

                const uint32_t aOff0 = (uint32_t)((arow * PA + k0 + acolb) * 2);
                // hoist aH(mt=0) above B loads so its latency overlaps B issue
                ldsm_x4(aH[0], aHb + aOff0);

                // B frags: ldsm_x4 covers 2 n-tiles per instruction
                #pragma unroll
                for (int p = 0; p < 2; p++) {
                    const uint32_t off =
                        (uint32_t)(((brow + p * 16) * PA + k0 + bcolb) * 2);
                    uint32_t r[4];
                    ldsm_x4(r, bHb + off);
                    bh[2 * p][0] = r[0]; bh[2 * p][1] = r[1];
                    bh[2 * p + 1][0] = r[2]; bh[2 * p + 1][1] = r[3];
                    ldsm_x4(r, bLb + off);
                    bl[2 * p][0] = r[0]; bl[2 * p][1] = r[1];
                    bl[2 * p + 1][0] = r[2]; bl[2 * p + 1][1] = r[3];
                }

                #pragma unroll
                for (int mt = 0; mt < 4; mt++) {
                    const uint32_t offA = aOff0 + (uint32_t)(mt * 16 * PA * 2);
                    // issue aL(mt) early; its first use is after 8 mma
                    ldsm_x4(aL, aLb + offA);
                    #pragma unroll
                    for (int nt = 0; nt < 4; nt++) mma16816(acc[mt][nt], aH[mt & 1], bh[nt]);
                    #pragma unroll
                    for (int nt = 0; nt < 4; nt++) mma16816(acc[mt][nt], aH[mt & 1], bl[nt]);
                    // prefetch next mt's aH; first use after 4 mma below
                    if (mt < 3) ldsm_x4(aH[(mt + 1) & 1], aHb + offA + (uint32_t)(16 * PA * 2));
                    #pragma unroll
                    for (int nt = 0; nt < 4; nt++) mma16816(acc[mt][nt], aL, bh[nt]);
                }
            }
            __syncthreads();
            if (i + 2 < nchunks) prefetch(c0 + i + 2, i & 1);
            CP_COMMIT();
        }
    }

    // ---------------- epilogue ----------------------------------------------
    const int mq = lane >> 2;
    const int nq = (lane & 3) * 2;

    if (MODE == 0) {
        const int region = n0 / F;      // 0=q 1=k 2=v
        if (region < 2) {
            __nv_bfloat16* Dh = region ? kh : qh;
            __nv_bfloat16* Dl = region ? kl : ql;
            const int nb = n0 - region * F;
            #pragma unroll
            for (int mt = 0; mt < 4; mt++) {
                const int r0 = m0 + wm + mt * 16 + mq;
                #pragma unroll
                for (int nt = 0; nt < 4; nt++) {
                    const int nl = nb + wn + nt * 8 + nq;
                    const int gn = n0 + wn + nt * 8 + nq;
                    float v0 = acc[mt][nt][0] + bias[gn];
                    float v1 = acc[mt][nt][1] + bias[gn + 1];
                    float v2 = acc[mt][nt][2] + bias[gn];
                    float v3 = acc[mt][nt][3] + bias[gn + 1];
                    __nv_bfloat16 h0, l0, h1, l1;
                    split_bf16(v0, h0, l0); split_bf16(v1, h1, l1);
                    *(__nv_bfloat162*)&Dh[(size_t)r0 * F + nl] = __nv_bfloat162(h0, h1);
                    *(__nv_bfloat162*)&Dl[(size_t)r0 * F + nl] = __nv_bfloat162(l0, l1);
                    split_bf16(v2, h0, l0); split_bf16(v3, h1, l1);
                    *(__nv_bfloat162*)&Dh[(size_t)(r0 + 8) * F + nl] = __nv_bfloat162(h0, h1);
                    *(__nv_bfloat162*)&Dl[(size_t)(r0 + 8) * F + nl] = __nv_bfloat162(l0, l1);
                }
            }
        } else {
            // v region: stage transposed tile in smem, write vT coalesced
            CP_WAIT0();
            __nv_bfloat16* smem_t = (__nv_bfloat16*)smem;
            const int vb = n0 - 2 * F;
            #pragma unroll
            for (int pass = 0; pass < 2; pass++) {
                __syncthreads();
                #pragma unroll
                for (int mt = 0; mt < 4; mt++) {
                    const int ml = wm + mt * 16 + mq;
                    #pragma unroll
                    for (int nt = 0; nt < 4; nt++) {
                        const int nl = wn + nt * 8 + nq;
                        const int gn = n0 + wn + nt * 8 + nq;
                        #pragma unroll
                        for (int e = 0; e < 4; e++) {
                            const int nn = nl + (e & 1);
                            const int mm = ml + (e >> 1) * 8;
                            float v = acc[mt][nt][e] + bias[gn + (e & 1)];
                            __nv_bfloat16 h = __float2bfloat16(v);
                            __nv_bfloat16 o = h;
                            if (pass) o = __float2bfloat16(v - __bfloat162float(h));
                            smem_t[nn * PT + mm] = o;
                        }
                    }
                }
                __syncthreads();
                __nv_bfloat16* D = pass ? vTl : vTh;
                const int r = tid >> 1;
                const int sg = (tid & 1) * 64;
                const uint4* src = (const uint4*)&smem_t[r * PT + sg];
                uint4* dst = (uint4*)&D[(size_t)(vb + r) * S + m0 + sg];
                #pragma unroll
                for (int j = 0; j < 8; j++) dst[j] = src[j];
            }
        }
    } else {
        #pragma unroll
        for (int mt = 0; mt < 4; mt++) {
            const int r0 = m0 + wm + mt * 16 + mq;
            #pragma unroll
            for (int nt = 0; nt < 4; nt++) {
                const int gn = n0 + wn + nt * 8 + nq;
                float2 p0, p1;
                p0.x = acc[mt][nt][0] * scale;  p0.y = acc[mt][nt][1] * scale;
                p1.x = acc[mt][nt][2] * scale;  p1.y = acc[mt][nt][3] * scale;
                *(float2*)&outf[(size_t)r0 * ldo + gn]       = p0;
                *(float2*)&outf[(size_t)(r0 + 8) * ldo + gn] = p1;
            }
        }
    }
}

// ---------------- fp32 -> bf16 hi/lo elementwise ----------------------------
__global__ __launch_bounds__(256) void split_convert_kernel(
    const float* __restrict__ in, __nv_bfloat16* __restrict__ h,
    __nv_bfloat16* __restrict__ l, size_t n4)
{
    for (size_t i = blockIdx.x * 256 + threadIdx.x; i < n4; i += (size_t)gridDim.x * 256) {
        float4 v = ((const float4*)in)[i];
        __nv_bfloat16 hh[4], ll[4];
        split_bf16(v.x, hh[0], ll[0]);
        split_bf16(v.y, hh[1], ll[1]);
        split_bf16(v.z, hh[2], ll[2]);
        split_bf16(v.w, hh[3], ll[3]);
        ((__nv_bfloat162*)h)[i * 2 + 0] = __nv_bfloat162(hh[0], hh[1]);
        ((__nv_bfloat162*)h)[i * 2 + 1] = __nv_bfloat162(hh[2], hh[3]);
        ((__nv_bfloat162*)l)[i * 2 + 0] = __nv_bfloat162(ll[0], ll[1]);
        ((__nv_bfloat162*)l)[i * 2 + 1] = __nv_bfloat162(ll[2], ll[3]);
    }
}

// ---------------- transpose + split: Wt[c][r] = W[r][c] ---------------------
__global__ __launch_bounds__(256) void transpose_split_kernel(
    const float* __restrict__ W, __nv_bfloat16* __restrict__ Th,
    __nv_bfloat16* __restrict__ Tl, int rows, int cols)
{
    __shared__ float tile[32][33];
    const int bx = blockIdx.x * 32;
    const int by = blockIdx.y * 32;
    const int tx = threadIdx.x & 31;
    const int ty = threadIdx.x >> 5;
    #pragma unroll
    for (int i = 0; i < 4; i++)
        tile[ty + i * 8][tx] = W[(size_t)(by + ty + i * 8) * cols + bx + tx];
    __syncthreads();
    #pragma unroll
    for (int i = 0; i < 4; i++) {
        const int orow = bx + ty + i * 8;
        const int ocol = by + tx;
        __nv_bfloat16 h, l;
        split_bf16(tile[tx][ty + i * 8], h, l);
        Th[(size_t)orow * rows + ocol] = h;
        Tl[(size_t)orow * rows + ocol] = l;
    }
}

// ---------------- softmax: fp32 scores -> att bf16 hi/lo --------------------
__global__ __launch_bounds__(256) void softmax_kernel(
    float* __restrict__ s, __nv_bfloat16* __restrict__ ah,
    __nv_bfloat16* __restrict__ al, int S, const int* __restrict__ np_ptr)
{
    const int i = blockIdx.x;
    const int np = *np_ptr;
    float* row = s + (size_t)i * S;
    __nv_bfloat16* rh = ah + (size_t)i * S;
    __nv_bfloat16* rl = al + (size_t)i * S;
    const int tid = threadIdx.x;
    __shared__ float red[256];

    if (i < np) {
        const __nv_bfloat16 z = __float2bfloat16(0.f);
        for (int j = tid; j < S; j += 256) { rh[j] = z; rl[j] = z; }
        return;
    }
    float m = -3.402823e38f;
    for (int j = np + tid; j <= i; j += 256) m = fmaxf(m, row[j]);
    red[tid] = m; __syncthreads();
    for (int off = 128; off > 0; off >>= 1) {
        if (tid < off) red[tid] = fmaxf(red[tid], red[tid + off]);
        __syncthreads();
    }
    m = red[0]; __syncthreads();

    float sum = 0.f;
    for (int j = np + tid; j <= i; j += 256) {
        float e = __expf(row[j] - m);
        row[j] = e;
        sum += e;
    }
    red[tid] = sum; __syncthreads();
    for (int off = 128; off > 0; off >>= 1) {
        if (tid < off) red[tid] += red[tid + off];
        __syncthreads();
    }
    const float inv = 1.f / red[0]; __syncthreads();

    for (int j = tid; j < S; j += 256) {
        float p = (j >= np && j <= i) ? row[j] * inv : 0.f;
        __nv_bfloat16 h, l;
        split_bf16(p, h, l);
        rh[j] = h; rl[j] = l;
    }
}

// ============================================================================
extern "C" void kernel_launch(void* const* d_in, const int* in_sizes, int n_in,
                              void* d_out, int out_size)
{
    const float* x  = (const float*)d_in[0];
    const float* W  = (const float*)d_in[1];
    const float* b  = (const float*)d_in[2];
    const int*   np = (const int*)  d_in[3];

    const int F3 = in_sizes[2];      // 6144
    const int F  = F3 / 3;           // 2048
    const int S  = in_sizes[0] / F;  // 4096
    float* out = (float*)d_out;

    __nv_bfloat16 *xh, *xl, *Wth, *Wtl, *qh, *ql, *kh, *kl, *vTh, *vTl, *atth, *attl;
    float* sc;
    cudaGetSymbolAddress((void**)&xh,  g_xh);   cudaGetSymbolAddress((void**)&xl,  g_xl);
    cudaGetSymbolAddress((void**)&Wth, g_Wth);  cudaGetSymbolAddress((void**)&Wtl, g_Wtl);
    cudaGetSymbolAddress((void**)&qh,  g_qh);   cudaGetSymbolAddress((void**)&ql,  g_ql);
    cudaGetSymbolAddress((void**)&kh,  g_kh);   cudaGetSymbolAddress((void**)&kl,  g_kl);
    cudaGetSymbolAddress((void**)&vTh, g_vTh);  cudaGetSymbolAddress((void**)&vTl, g_vTl);
    cudaGetSymbolAddress((void**)&sc,  g_scores);
    cudaGetSymbolAddress((void**)&atth, g_atth); cudaGetSymbolAddress((void**)&attl, g_attl);

    cudaFuncSetAttribute(hmma_gemm<0>, cudaFuncAttributeMaxDynamicSharedMemorySize, SMEM_BYTES);
    cudaFuncSetAttribute(hmma_gemm<1>, cudaFuncAttributeMaxDynamicSharedMemorySize, SMEM_BYTES);
    cudaFuncSetAttribute(hmma_gemm<2>, cudaFuncAttributeMaxDynamicSharedMemorySize, SMEM_BYTES);

    const float scale = 1.0f / sqrtf((float)F);

    split_convert_kernel<<<4096, 256>>>(x, xh, xl, (size_t)S * F / 4);
    transpose_split_kernel<<<dim3(F3 / 32, F / 32), 256>>>(W, Wth, Wtl, F, F3);

    hmma_gemm<0><<<dim3(F3 / 128, S / 128), 256, SMEM_BYTES>>>(
        xh, xl, F, Wth, Wtl, F, F, b, 1.0f, nullptr, 0,
        qh, ql, kh, kl, vTh, vTl, F, S, np);

    hmma_gemm<1><<<dim3(S / 128, S / 128), 256, SMEM_BYTES>>>(
        qh, ql, F, kh, kl, F, F, nullptr, scale, sc, S,
        nullptr, nullptr, nullptr, nullptr, nullptr, nullptr, F, S, np);

    softmax_kernel<<<S, 256>>>(sc, atth, attl, S, np);

    hmma_gemm<2><<<dim3(F / 128, S / 128), 256, SMEM_BYTES>>>(
        atth, attl, S, vTh, vTl, S, S, nullptr, 1.0f, out, F,
        nullptr, nullptr, nullptr, nullptr, nullptr, nullptr, F, S, np);
}

// round 7
// speedup vs baseline: 1.3270x; 1.1504x over previous
#include <cuda_runtime.h>
#include <cuda_fp16.h>
#include <math.h>
#include <stdint.h>

// ============================================================================
// PaddedSHCSA via mma.sync fp16 split hi/lo.
//  qkv   : 3-pass (AhBh+AhBl+AlBh)  -> err ~2^-22
//  scores: 2-pass (AhBh+AhBl), A = q hi-only
//  out   : 2-pass (AhBh+AhBl), A = att hi-only
// 2-pass kernels: 3 smem tiles/stage, 3 stages, ONE barrier/chunk.
// ============================================================================

#define S_DIM   4096
#define F_DIM   2048
#define F3_DIM  6144

__device__ __half g_xh [(size_t)S_DIM * F_DIM];
__device__ __half g_xl [(size_t)S_DIM * F_DIM];
__device__ __half g_Wth[(size_t)F3_DIM * F_DIM];   // W^T [3F][F]
__device__ __half g_Wtl[(size_t)F3_DIM * F_DIM];
__device__ __half g_qh [(size_t)S_DIM * F_DIM];    // hi only
__device__ __half g_kh [(size_t)S_DIM * F_DIM];
__device__ __half g_kl [(size_t)S_DIM * F_DIM];
__device__ __half g_vTh[(size_t)F_DIM * S_DIM];    // v^T [F][S]
__device__ __half g_vTl[(size_t)F_DIM * S_DIM];
__device__ float  g_scores[(size_t)S_DIM * S_DIM];
__device__ __half g_atth[(size_t)S_DIM * S_DIM];   // hi only

// ---------------- low-level helpers -----------------------------------------
__device__ __forceinline__ uint32_t smem_u32(const void* p) {
    uint32_t a;
    asm("{ .reg .u64 t; cvta.to.shared.u64 t, %1; cvt.u32.u64 %0, t; }" : "=r"(a) : "l"(p));
    return a;
}
#define CP_ASYNC16(dst_u32, src_ptr) \
    asm volatile("cp.async.cg.shared.global [%0], [%1], 16;" :: "r"(dst_u32), "l"(src_ptr))
#define CP_COMMIT()  asm volatile("cp.async.commit_group;" ::: "memory")
#define CP_WAIT1()   asm volatile("cp.async.wait_group 1;" ::: "memory")
#define CP_WAIT0()   asm volatile("cp.async.wait_group 0;" ::: "memory")

__device__ __forceinline__ void ldsm_x4(uint32_t* r, uint32_t addr) {
    asm volatile("ldmatrix.sync.aligned.m8n8.x4.shared.b16 {%0,%1,%2,%3}, [%4];"
        : "=r"(r[0]), "=r"(r[1]), "=r"(r[2]), "=r"(r[3]) : "r"(addr));
}
__device__ __forceinline__ void mma16816(float* c, const uint32_t* a, const uint32_t* b) {
    asm volatile("mma.sync.aligned.m16n8k16.row.col.f32.f16.f16.f32 "
        "{%0,%1,%2,%3}, {%4,%5,%6,%7}, {%8,%9}, {%0,%1,%2,%3};"
        : "+f"(c[0]), "+f"(c[1]), "+f"(c[2]), "+f"(c[3])
        : "r"(a[0]), "r"(a[1]), "r"(a[2]), "r"(a[3]), "r"(b[0]), "r"(b[1]));
}
__device__ __forceinline__ void split_h(float v, __half& h, __half& l) {
    h = __float2half(v);
    l = __float2half(v - __half2float(h));
}

// ---------------- smem layout -----------------------------------------------
static constexpr int PA = 40;                        // pitch halves (80B, conflict-free)
static constexpr int TILE_B = 128 * PA * 2;          // 10240 B
static constexpr int STAGE_B3 = 4 * TILE_B;          // MODE0: Ah Al Bh Bl
static constexpr int STAGE_B2 = 3 * TILE_B;          // MODE1/2: Ah Bh Bl
static constexpr int SMEM_M0 = 2 * STAGE_B3;         // 81920
static constexpr int SMEM_M12 = 3 * STAGE_B2;        // 92160
static constexpr int PT = 136;

// ============================================================================
template<int MODE>
__global__ __launch_bounds__(256, 2) void hmma_gemm(
    const __half* __restrict__ Ah, const __half* __restrict__ Al, int lda,
    const __half* __restrict__ Bh, const __half* __restrict__ Bl, int ldb,
    int K, const float* __restrict__ bias, float scale,
    float* __restrict__ outf, int ldo,
    __half* __restrict__ qh,
    __half* __restrict__ kh, __half* __restrict__ kl,
    __half* __restrict__ vTh, __half* __restrict__ vTl,
    int F, int S, const int* __restrict__ np_ptr)
{
    const int m0 = blockIdx.y * 128;
    const int n0 = blockIdx.x * 128;
    const int np = *np_ptr;

    if (MODE == 0) { if (m0 + 128 <= np) return; }
    if (MODE == 1) {
        if (n0 > m0) return;
        if (m0 + 128 <= np) return;
        if (n0 + 128 <= np) return;
    }

    int c0 = 0, c1 = K >> 5;
    if (MODE == 2) { c0 = np >> 5; c1 = (m0 + 128) >> 5; }
    const int nchunks = c1 - c0;

    extern __shared__ __align__(128) char smem[];
    const uint32_t sbase = smem_u32(smem);

    const int tid  = threadIdx.x;
    const int wid  = tid >> 5;
    const int lane = tid & 31;
    const int wm   = (wid >> 2) * 64;
    const int wn   = (wid & 3) * 32;

    float acc[4][4][4];
    #pragma unroll
    for (int i = 0; i < 4; i++)
        #pragma unroll
        for (int j = 0; j < 4; j++)
            #pragma unroll
            for (int e = 0; e < 4; e++) acc[i][j][e] = 0.f;

    const int STAGE_B = (MODE == 0) ? STAGE_B3 : STAGE_B2;

    auto prefetch = [&](int c, int stage) {
        const int kc = c << 5;
        const uint32_t st = sbase + stage * STAGE_B;
        #pragma unroll
        for (int t = 0; t < 2; t++) {
            const int idx = tid + t * 256;
            const int r   = idx >> 2;
            const int seg = idx & 3;
            const uint32_t d = (uint32_t)(r * PA * 2 + seg * 16);
            if (MODE == 0) {
                CP_ASYNC16(st + 0 * TILE_B + d, &Ah[(size_t)(m0 + r) * lda + kc + seg * 8]);
                CP_ASYNC16(st + 1 * TILE_B + d, &Al[(size_t)(m0 + r) * lda + kc + seg * 8]);
                CP_ASYNC16(st + 2 * TILE_B + d, &Bh[(size_t)(n0 + r) * ldb + kc + seg * 8]);
                CP_ASYNC16(st + 3 * TILE_B + d, &Bl[(size_t)(n0 + r) * ldb + kc + seg * 8]);
            } else {
                CP_ASYNC16(st + 0 * TILE_B + d, &Ah[(size_t)(m0 + r) * lda + kc + seg * 8]);
                CP_ASYNC16(st + 1 * TILE_B + d, &Bh[(size_t)(n0 + r) * ldb + kc + seg * 8]);
                CP_ASYNC16(st + 2 * TILE_B + d, &Bl[(size_t)(n0 + r) * ldb + kc + seg * 8]);
            }
        }
    };

    const int arow = wm + (lane & 15);
    const int acolb = (lane >> 4) * 8;
    const int brow = wn + (lane & 7) + ((lane >> 4) << 3);
    const int bcolb = ((lane >> 3) & 1) << 3;

    if (nchunks > 0 && MODE == 0) {
        // ---- 3-pass, 2 stages, 2 barriers ----
        prefetch(c0, 0); CP_COMMIT();
        if (nchunks > 1) prefetch(c0 + 1, 1);
        CP_COMMIT();
        for (int i = 0; i < nchunks; i++) {
            CP_WAIT1();
            __syncthreads();
            const uint32_t st = sbase + (i & 1) * STAGE_B3;
            const uint32_t aHb = st, aLb = st + TILE_B;
            const uint32_t bHb = st + 2 * TILE_B, bLb = st + 3 * TILE_B;
            #pragma unroll
            for (int ks = 0; ks < 2; ks++) {
                const int k0 = ks * 16;
                uint32_t aH[2][4], aL[4];
                uint32_t bh[4][2], bl[4][2];
                const uint32_t aOff0 = (uint32_t)((arow * PA + k0 + acolb) * 2);
                ldsm_x4(aH[0], aHb + aOff0);
                #pragma unroll
                for (int p = 0; p < 2; p++) {
                    const uint32_t off = (uint32_t)(((brow + p * 16) * PA + k0 + bcolb) * 2);
                    uint32_t r[4];
                    ldsm_x4(r, bHb + off);
                    bh[2 * p][0] = r[0]; bh[2 * p][1] = r[1];
                    bh[2 * p + 1][0] = r[2]; bh[2 * p + 1][1] = r[3];
                    ldsm_x4(r, bLb + off);
                    bl[2 * p][0] = r[0]; bl[2 * p][1] = r[1];
                    bl[2 * p + 1][0] = r[2]; bl[2 * p + 1][1] = r[3];
                }
                #pragma unroll
                for (int mt = 0; mt < 4; mt++) {
                    const uint32_t offA = aOff0 + (uint32_t)(mt * 16 * PA * 2);
                    ldsm_x4(aL, aLb + offA);
                    #pragma unroll
                    for (int nt = 0; nt < 4; nt++) mma16816(acc[mt][nt], aH[mt & 1], bh[nt]);
                    #pragma unroll
                    for (int nt = 0; nt < 4; nt++) mma16816(acc[mt][nt], aH[mt & 1], bl[nt]);
                    if (mt < 3) ldsm_x4(aH[(mt + 1) & 1], aHb + offA + (uint32_t)(16 * PA * 2));
                    #pragma unroll
                    for (int nt = 0; nt < 4; nt++) mma16816(acc[mt][nt], aL, bh[nt]);
                }
            }
            __syncthreads();
            if (i + 2 < nchunks) prefetch(c0 + i + 2, i & 1);
            CP_COMMIT();
        }
    } else if (nchunks > 0) {
        // ---- 2-pass, 3 stages, ONE barrier ----
        prefetch(c0, 0); CP_COMMIT();
        if (nchunks > 1) prefetch(c0 + 1, 1);
        CP_COMMIT();
        int s_cur = 0, s_pf = 2;
        for (int i = 0; i < nchunks; i++) {
            CP_WAIT1();
            __syncthreads();
            if (i + 2 < nchunks) prefetch(c0 + i + 2, s_pf);
            CP_COMMIT();
            const uint32_t st = sbase + s_cur * STAGE_B2;
            const uint32_t aHb = st;
            const uint32_t bHb = st + TILE_B, bLb = st + 2 * TILE_B;
            #pragma unroll
            for (int ks = 0; ks < 2; ks++) {
                const int k0 = ks * 16;
                uint32_t aH[2][4];
                uint32_t bh[4][2], bl[4][2];
                const uint32_t aOff0 = (uint32_t)((arow * PA + k0 + acolb) * 2);
                ldsm_x4(aH[0], aHb + aOff0);
                #pragma unroll
                for (int p = 0; p < 2; p++) {
                    const uint32_t off = (uint32_t)(((brow + p * 16) * PA + k0 + bcolb) * 2);
                    uint32_t r[4];
                    ldsm_x4(r, bHb + off);
                    bh[2 * p][0] = r[0]; bh[2 * p][1] = r[1];
                    bh[2 * p + 1][0] = r[2]; bh[2 * p + 1][1] = r[3];
                    ldsm_x4(r, bLb + off);
                    bl[2 * p][0] = r[0]; bl[2 * p][1] = r[1];
                    bl[2 * p + 1][0] = r[2]; bl[2 * p + 1][1] = r[3];
                }
                #pragma unroll
                for (int mt = 0; mt < 4; mt++) {
                    const uint32_t offA = aOff0 + (uint32_t)(mt * 16 * PA * 2);
                    #pragma unroll
                    for (int nt = 0; nt < 4; nt++) mma16816(acc[mt][nt], aH[mt & 1], bh[nt]);
                    if (mt < 3) ldsm_x4(aH[(mt + 1) & 1], aHb + offA + (uint32_t)(16 * PA * 2));
                    #pragma unroll
                    for (int nt = 0; nt < 4; nt++) mma16816(acc[mt][nt], aH[mt & 1], bl[nt]);
                }
            }
            s_cur = (s_cur == 2) ? 0 : s_cur + 1;
            s_pf  = (s_pf  == 2) ? 0 : s_pf  + 1;
        }
    }

    // ---------------- epilogue ----------------------------------------------
    const int mq = lane >> 2;
    const int nq = (lane & 3) * 2;

    if (MODE == 0) {
        const int region = n0 / F;      // 0=q 1=k 2=v
        if (region == 0) {
            #pragma unroll
            for (int mt = 0; mt < 4; mt++) {
                const int r0 = m0 + wm + mt * 16 + mq;
                #pragma unroll
                for (int nt = 0; nt < 4; nt++) {
                    const int nl = n0 + wn + nt * 8 + nq;
                    __half h0 = __float2half(acc[mt][nt][0] + bias[nl]);
                    __half h1 = __float2half(acc[mt][nt][1] + bias[nl + 1]);
                    *(__half2*)&qh[(size_t)r0 * F + nl] = __half2(h0, h1);
                    h0 = __float2half(acc[mt][nt][2] + bias[nl]);
                    h1 = __float2half(acc[mt][nt][3] + bias[nl + 1]);
                    *(__half2*)&qh[(size_t)(r0 + 8) * F + nl] = __half2(h0, h1);
                }
            }
        } else if (region == 1) {
            const int nb = n0 - F;
            #pragma unroll
            for (int mt = 0; mt < 4; mt++) {
                const int r0 = m0 + wm + mt * 16 + mq;
                #pragma unroll
                for (int nt = 0; nt < 4; nt++) {
                    const int nl = nb + wn + nt * 8 + nq;
                    const int gn = n0 + wn + nt * 8 + nq;
                    float v0 = acc[mt][nt][0] + bias[gn];
                    float v1 = acc[mt][nt][1] + bias[gn + 1];
                    float v2 = acc[mt][nt][2] + bias[gn];
                    float v3 = acc[mt][nt][3] + bias[gn + 1];
                    __half h0, l0, h1, l1;
                    split_h(v0, h0, l0); split_h(v1, h1, l1);
                    *(__half2*)&kh[(size_t)r0 * F + nl] = __half2(h0, h1);
                    *(__half2*)&kl[(size_t)r0 * F + nl] = __half2(l0, l1);
                    split_h(v2, h0, l0); split_h(v3, h1, l1);
                    *(__half2*)&kh[(size_t)(r0 + 8) * F + nl] = __half2(h0, h1);
                    *(__half2*)&kl[(size_t)(r0 + 8) * F + nl] = __half2(l0, l1);
                }
            }
        } else {
            // v region: stage transposed tile in smem, write vT coalesced
            CP_WAIT0();
            __half* smem_t = (__half*)smem;
            const int vb = n0 - 2 * F;
            #pragma unroll
            for (int pass = 0; pass < 2; pass++) {
                __syncthreads();
                #pragma unroll
                for (int mt = 0; mt < 4; mt++) {
                    const int ml = wm + mt * 16 + mq;
                    #pragma unroll
                    for (int nt = 0; nt < 4; nt++) {
                        const int nl = wn + nt * 8 + nq;
                        const int gn = n0 + wn + nt * 8 + nq;
                        #pragma unroll
                        for (int e = 0; e < 4; e++) {
                            const int nn = nl + (e & 1);
                            const int mm = ml + (e >> 1) * 8;
                            float v = acc[mt][nt][e] + bias[gn + (e & 1)];
                            __half h = __float2half(v);
                            __half o = h;
                            if (pass) o = __float2half(v - __half2float(h));
                            smem_t[nn * PT + mm] = o;
                        }
                    }
                }
                __syncthreads();
                __half* D = pass ? vTl : vTh;
                const int r = tid >> 1;
                const int sg = (tid & 1) * 64;
                const uint4* src = (const uint4*)&smem_t[r * PT + sg];
                uint4* dst = (uint4*)&D[(size_t)(vb + r) * S + m0 + sg];
                #pragma unroll
                for (int j = 0; j < 8; j++) dst[j] = src[j];
            }
        }
    } else {
        #pragma unroll
        for (int mt = 0; mt < 4; mt++) {
            const int r0 = m0 + wm + mt * 16 + mq;
            #pragma unroll
            for (int nt = 0; nt < 4; nt++) {
                const int gn = n0 + wn + nt * 8 + nq;
                float2 p0, p1;
                p0.x = acc[mt][nt][0] * scale;  p0.y = acc[mt][nt][1] * scale;
                p1.x = acc[mt][nt][2] * scale;  p1.y = acc[mt][nt][3] * scale;
                *(float2*)&outf[(size_t)r0 * ldo + gn]       = p0;
                *(float2*)&outf[(size_t)(r0 + 8) * ldo + gn] = p1;
            }
        }
    }
}

// ---------------- fp32 -> fp16 hi/lo elementwise ----------------------------
__global__ __launch_bounds__(256) void split_convert_kernel(
    const float* __restrict__ in, __half* __restrict__ h,
    __half* __restrict__ l, size_t n4)
{
    for (size_t i = blockIdx.x * 256 + threadIdx.x; i < n4; i += (size_t)gridDim.x * 256) {
        float4 v = ((const float4*)in)[i];
        __half hh[4], ll[4];
        split_h(v.x, hh[0], ll[0]);
        split_h(v.y, hh[1], ll[1]);
        split_h(v.z, hh[2], ll[2]);
        split_h(v.w, hh[3], ll[3]);
        ((__half2*)h)[i * 2 + 0] = __half2(hh[0], hh[1]);
        ((__half2*)h)[i * 2 + 1] = __half2(hh[2], hh[3]);
        ((__half2*)l)[i * 2 + 0] = __half2(ll[0], ll[1]);
        ((__half2*)l)[i * 2 + 1] = __half2(ll[2], ll[3]);
    }
}

// ---------------- transpose + split: Wt[c][r] = W[r][c] ---------------------
__global__ __launch_bounds__(256) void transpose_split_kernel(
    const float* __restrict__ W, __half* __restrict__ Th,
    __half* __restrict__ Tl, int rows, int cols)
{
    __shared__ float tile[32][33];
    const int bx = blockIdx.x * 32;
    const int by = blockIdx.y * 32;
    const int tx = threadIdx.x & 31;
    const int ty = threadIdx.x >> 5;
    #pragma unroll
    for (int i = 0; i < 4; i++)
        tile[ty + i * 8][tx] = W[(size_t)(by + ty + i * 8) * cols + bx + tx];
    __syncthreads();
    #pragma unroll
    for (int i = 0; i < 4; i++) {
        const int orow = bx + ty + i * 8;
        const int ocol = by + tx;
        __half h, l;
        split_h(tile[tx][ty + i * 8], h, l);
        Th[(size_t)orow * rows + ocol] = h;
        Tl[(size_t)orow * rows + ocol] = l;
    }
}

// ---------------- softmax: fp32 scores -> att fp16 (hi only) ----------------
__global__ __launch_bounds__(256) void softmax_kernel(
    float* __restrict__ s, __half* __restrict__ ah,
    int S, const int* __restrict__ np_ptr)
{
    const int i = blockIdx.x;
    const int np = *np_ptr;
    float* row = s + (size_t)i * S;
    __half* rh = ah + (size_t)i * S;
    const int tid = threadIdx.x;
    __shared__ float red[256];
    const int fill_end = ((i >> 7) + 1) << 7;   // end of this row's 128-block

    if (i < np) {
        const __half z = __float2half(0.f);
        for (int j = tid; j < fill_end; j += 256) rh[j] = z;
        return;
    }
    float m = -3.402823e38f;
    for (int j = np + tid; j <= i; j += 256) m = fmaxf(m, row[j]);
    red[tid] = m; __syncthreads();
    for (int off = 128; off > 0; off >>= 1) {
        if (tid < off) red[tid] = fmaxf(red[tid], red[tid + off]);
        __syncthreads();
    }
    m = red[0]; __syncthreads();

    float sum = 0.f;
    for (int j = np + tid; j <= i; j += 256) {
        float e = __expf(row[j] - m);
        row[j] = e;
        sum += e;
    }
    red[tid] = sum; __syncthreads();
    for (int off = 128; off > 0; off >>= 1) {
        if (tid < off) red[tid] += red[tid + off];
        __syncthreads();
    }
    const float inv = 1.f / red[0]; __syncthreads();

    for (int j = tid; j < fill_end; j += 256) {
        float p = (j >= np && j <= i) ? row[j] * inv : 0.f;
        rh[j] = __float2half(p);
    }
}

// ============================================================================
extern "C" void kernel_launch(void* const* d_in, const int* in_sizes, int n_in,
                              void* d_out, int out_size)
{
    const float* x  = (const float*)d_in[0];
    const float* W  = (const float*)d_in[1];
    const float* b  = (const float*)d_in[2];
    const int*   np = (const int*)  d_in[3];

    const int F3 = in_sizes[2];      // 6144
    const int F  = F3 / 3;           // 2048
    const int S  = in_sizes[0] / F;  // 4096
    float* out = (float*)d_out;

    __half *xh, *xl, *Wth, *Wtl, *qh, *kh, *kl, *vTh, *vTl, *atth;
    float* sc;
    cudaGetSymbolAddress((void**)&xh,  g_xh);   cudaGetSymbolAddress((void**)&xl,  g_xl);
    cudaGetSymbolAddress((void**)&Wth, g_Wth);  cudaGetSymbolAddress((void**)&Wtl, g_Wtl);
    cudaGetSymbolAddress((void**)&qh,  g_qh);
    cudaGetSymbolAddress((void**)&kh,  g_kh);   cudaGetSymbolAddress((void**)&kl,  g_kl);
    cudaGetSymbolAddress((void**)&vTh, g_vTh);  cudaGetSymbolAddress((void**)&vTl, g_vTl);
    cudaGetSymbolAddress((void**)&sc,  g_scores);
    cudaGetSymbolAddress((void**)&atth, g_atth);

    cudaFuncSetAttribute(hmma_gemm<0>, cudaFuncAttributeMaxDynamicSharedMemorySize, SMEM_M0);
    cudaFuncSetAttribute(hmma_gemm<1>, cudaFuncAttributeMaxDynamicSharedMemorySize, SMEM_M12);
    cudaFuncSetAttribute(hmma_gemm<2>, cudaFuncAttributeMaxDynamicSharedMemorySize, SMEM_M12);

    const float scale = 1.0f / sqrtf((float)F);

    split_convert_kernel<<<4096, 256>>>(x, xh, xl, (size_t)S * F / 4);
    transpose_split_kernel<<<dim3(F3 / 32, F / 32), 256>>>(W, Wth, Wtl, F, F3);

    // qkv = x@W + b  (3-pass) -> qh, kh/kl, vT h/l
    hmma_gemm<0><<<dim3(F3 / 128, S / 128), 256, SMEM_M0>>>(
        xh, xl, F, Wth, Wtl, F, F, b, 1.0f, nullptr, 0,
        qh, kh, kl, vTh, vTl, F, S, np);

    // scores = scale * q@k^T  (2-pass, A = qh)
    hmma_gemm<1><<<dim3(S / 128, S / 128), 256, SMEM_M12>>>(
        qh, nullptr, F, kh, kl, F, F, nullptr, scale, sc, S,
        nullptr, nullptr, nullptr, nullptr, nullptr, F, S, np);

    softmax_kernel<<<S, 256>>>(sc, atth, S, np);

    // out = att@v  (2-pass, A = atth)
    hmma_gemm<2><<<dim3(F / 128, S / 128), 256, SMEM_M12>>>(
        atth, nullptr, S, vTh, vTl, S, S, nullptr, 1.0f, out, F,
        nullptr, nullptr, nullptr, nullptr, nullptr, F, S, np);
}

// round 8
// speedup vs baseline: 1.6639x; 1.2539x over previous
#include <cuda_runtime.h>
#include <cuda_fp16.h>
#include <math.h>
#include <stdint.h>

// ============================================================================
// PaddedSHCSA via mma.sync fp16, ALL GEMMs 2-pass split (Ah·Bh + Ah·Bl):
//  qkv    = xh @ (Wth + Wtl)     -> q hi, k hi/lo, vT hi/lo
//  scores = qh @ (kh + kl)^T * scale
//  out    = atth @ (vTh + vTl)^T
// One unified kernel: 3 smem tiles/stage, 3-stage ring, ONE barrier/chunk.
// Calibrated error model: ~2.8e-4 per dropped lo term -> total ~5.5e-4 < 1e-3.
// ============================================================================

#define S_DIM   4096
#define F_DIM   2048
#define F3_DIM  6144

__device__ __half g_xh [(size_t)S_DIM * F_DIM];
__device__ __half g_Wth[(size_t)F3_DIM * F_DIM];   // W^T hi [3F][F]
__device__ __half g_Wtl[(size_t)F3_DIM * F_DIM];   // W^T lo
__device__ __half g_qh [(size_t)S_DIM * F_DIM];
__device__ __half g_kh [(size_t)S_DIM * F_DIM];
__device__ __half g_kl [(size_t)S_DIM * F_DIM];
__device__ __half g_vTh[(size_t)F_DIM * S_DIM];    // v^T [F][S]
__device__ __half g_vTl[(size_t)F_DIM * S_DIM];
__device__ float  g_scores[(size_t)S_DIM * S_DIM];
__device__ __half g_atth[(size_t)S_DIM * S_DIM];

// ---------------- low-level helpers -----------------------------------------
__device__ __forceinline__ uint32_t smem_u32(const void* p) {
    uint32_t a;
    asm("{ .reg .u64 t; cvta.to.shared.u64 t, %1; cvt.u32.u64 %0, t; }" : "=r"(a) : "l"(p));
    return a;
}
#define CP_ASYNC16(dst_u32, src_ptr) \
    asm volatile("cp.async.cg.shared.global [%0], [%1], 16;" :: "r"(dst_u32), "l"(src_ptr))
#define CP_COMMIT()  asm volatile("cp.async.commit_group;" ::: "memory")
#define CP_WAIT1()   asm volatile("cp.async.wait_group 1;" ::: "memory")
#define CP_WAIT0()   asm volatile("cp.async.wait_group 0;" ::: "memory")

__device__ __forceinline__ void ldsm_x4(uint32_t* r, uint32_t addr) {
    asm volatile("ldmatrix.sync.aligned.m8n8.x4.shared.b16 {%0,%1,%2,%3}, [%4];"
        : "=r"(r[0]), "=r"(r[1]), "=r"(r[2]), "=r"(r[3]) : "r"(addr));
}
__device__ __forceinline__ void mma16816(float* c, const uint32_t* a, const uint32_t* b) {
    asm volatile("mma.sync.aligned.m16n8k16.row.col.f32.f16.f16.f32 "
        "{%0,%1,%2,%3}, {%4,%5,%6,%7}, {%8,%9}, {%0,%1,%2,%3};"
        : "+f"(c[0]), "+f"(c[1]), "+f"(c[2]), "+f"(c[3])
        : "r"(a[0]), "r"(a[1]), "r"(a[2]), "r"(a[3]), "r"(b[0]), "r"(b[1]));
}
__device__ __forceinline__ void split_h(float v, __half& h, __half& l) {
    h = __float2half(v);
    l = __float2half(v - __half2float(h));
}

// ---------------- smem layout -----------------------------------------------
static constexpr int PA = 40;                        // pitch halves (80B row)
static constexpr int TILE_B = 128 * PA * 2;          // 10240 B
static constexpr int STAGE_B = 3 * TILE_B;           // Ah Bh Bl = 30720 B
static constexpr int SMEM_BYTES = 3 * STAGE_B;       // 92160 B (2 CTAs/SM ok)
static constexpr int PT = 136;

// ============================================================================
// C[m0:+128, n0:+128] = sum_k Ah[m][k]*(Bh+Bl)[n][k]
// MODE 0: qkv (bias; -> q hi / k hi+lo / vT hi+lo)
// MODE 1: scores (*scale -> fp32; causal/pad block skip)
// MODE 2: out (k range [np, m0+128); fp32 -> d_out)
// ============================================================================
template<int MODE>
__global__ __launch_bounds__(256, 2) void hmma_gemm(
    const __half* __restrict__ Ah, int lda,
    const __half* __restrict__ Bh, const __half* __restrict__ Bl, int ldb,
    int K, const float* __restrict__ bias, float scale,
    float* __restrict__ outf, int ldo,
    __half* __restrict__ qh,
    __half* __restrict__ kh, __half* __restrict__ kl,
    __half* __restrict__ vTh, __half* __restrict__ vTl,
    int F, int S, const int* __restrict__ np_ptr)
{
    const int m0 = blockIdx.y * 128;
    const int n0 = blockIdx.x * 128;
    const int np = *np_ptr;

    if (MODE == 0) { if (m0 + 128 <= np) return; }
    if (MODE == 1) {
        if (n0 > m0) return;
        if (m0 + 128 <= np) return;
        if (n0 + 128 <= np) return;
    }

    int c0 = 0, c1 = K >> 5;
    if (MODE == 2) { c0 = np >> 5; c1 = (m0 + 128) >> 5; }
    const int nchunks = c1 - c0;

    extern __shared__ __align__(128) char smem[];
    const uint32_t sbase = smem_u32(smem);

    const int tid  = threadIdx.x;
    const int wid  = tid >> 5;
    const int lane = tid & 31;
    const int wm   = (wid >> 2) * 64;
    const int wn   = (wid & 3) * 32;

    float acc[4][4][4];
    #pragma unroll
    for (int i = 0; i < 4; i++)
        #pragma unroll
        for (int j = 0; j < 4; j++)
            #pragma unroll
            for (int e = 0; e < 4; e++) acc[i][j][e] = 0.f;

    auto prefetch = [&](int c, int stage) {
        const int kc = c << 5;
        const uint32_t st = sbase + stage * STAGE_B;
        #pragma unroll
        for (int t = 0; t < 2; t++) {
            const int idx = tid + t * 256;
            const int r   = idx >> 2;
            const int seg = idx & 3;
            const uint32_t d = (uint32_t)(r * PA * 2 + seg * 16);
            CP_ASYNC16(st + 0 * TILE_B + d, &Ah[(size_t)(m0 + r) * lda + kc + seg * 8]);
            CP_ASYNC16(st + 1 * TILE_B + d, &Bh[(size_t)(n0 + r) * ldb + kc + seg * 8]);
            CP_ASYNC16(st + 2 * TILE_B + d, &Bl[(size_t)(n0 + r) * ldb + kc + seg * 8]);
        }
    };

    const int arow = wm + (lane & 15);
    const int acolb = (lane >> 4) * 8;
    const int brow = wn + (lane & 7) + ((lane >> 4) << 3);
    const int bcolb = ((lane >> 3) & 1) << 3;

    if (nchunks > 0) {
        prefetch(c0, 0); CP_COMMIT();
        if (nchunks > 1) prefetch(c0 + 1, 1);
        CP_COMMIT();
        int s_cur = 0, s_pf = 2;
        for (int i = 0; i < nchunks; i++) {
            CP_WAIT1();
            __syncthreads();
            if (i + 2 < nchunks) prefetch(c0 + i + 2, s_pf);
            CP_COMMIT();
            const uint32_t st = sbase + s_cur * STAGE_B;
            const uint32_t aHb = st;
            const uint32_t bHb = st + TILE_B, bLb = st + 2 * TILE_B;
            #pragma unroll
            for (int ks = 0; ks < 2; ks++) {
                const int k0 = ks * 16;
                uint32_t aH[2][4];
                uint32_t bh[4][2], bl[4][2];
                const uint32_t aOff0 = (uint32_t)((arow * PA + k0 + acolb) * 2);
                ldsm_x4(aH[0], aHb + aOff0);
                #pragma unroll
                for (int p = 0; p < 2; p++) {
                    const uint32_t off = (uint32_t)(((brow + p * 16) * PA + k0 + bcolb) * 2);
                    uint32_t r[4];
                    ldsm_x4(r, bHb + off);
                    bh[2 * p][0] = r[0]; bh[2 * p][1] = r[1];
                    bh[2 * p + 1][0] = r[2]; bh[2 * p + 1][1] = r[3];
                    ldsm_x4(r, bLb + off);
                    bl[2 * p][0] = r[0]; bl[2 * p][1] = r[1];
                    bl[2 * p + 1][0] = r[2]; bl[2 * p + 1][1] = r[3];
                }
                #pragma unroll
                for (int mt = 0; mt < 4; mt++) {
                    const uint32_t offA = aOff0 + (uint32_t)(mt * 16 * PA * 2);
                    #pragma unroll
                    for (int nt = 0; nt < 4; nt++) mma16816(acc[mt][nt], aH[mt & 1], bh[nt]);
                    if (mt < 3) ldsm_x4(aH[(mt + 1) & 1], aHb + offA + (uint32_t)(16 * PA * 2));
                    #pragma unroll
                    for (int nt = 0; nt < 4; nt++) mma16816(acc[mt][nt], aH[mt & 1], bl[nt]);
                }
            }
            s_cur = (s_cur == 2) ? 0 : s_cur + 1;
            s_pf  = (s_pf  == 2) ? 0 : s_pf  + 1;
        }
    }

    // ---------------- epilogue ----------------------------------------------
    const int mq = lane >> 2;
    const int nq = (lane & 3) * 2;

    if (MODE == 0) {
        const int region = n0 / F;      // 0=q 1=k 2=v
        if (region == 0) {
            #pragma unroll
            for (int mt = 0; mt < 4; mt++) {
                const int r0 = m0 + wm + mt * 16 + mq;
                #pragma unroll
                for (int nt = 0; nt < 4; nt++) {
                    const int nl = n0 + wn + nt * 8 + nq;
                    __half h0 = __float2half(acc[mt][nt][0] + bias[nl]);
                    __half h1 = __float2half(acc[mt][nt][1] + bias[nl + 1]);
                    *(__half2*)&qh[(size_t)r0 * F + nl] = __half2(h0, h1);
                    h0 = __float2half(acc[mt][nt][2] + bias[nl]);
                    h1 = __float2half(acc[mt][nt][3] + bias[nl + 1]);
                    *(__half2*)&qh[(size_t)(r0 + 8) * F + nl] = __half2(h0, h1);
                }
            }
        } else if (region == 1) {
            const int nb = n0 - F;
            #pragma unroll
            for (int mt = 0; mt < 4; mt++) {
                const int r0 = m0 + wm + mt * 16 + mq;
                #pragma unroll
                for (int nt = 0; nt < 4; nt++) {
                    const int nl = nb + wn + nt * 8 + nq;
                    const int gn = n0 + wn + nt * 8 + nq;
                    float v0 = acc[mt][nt][0] + bias[gn];
                    float v1 = acc[mt][nt][1] + bias[gn + 1];
                    float v2 = acc[mt][nt][2] + bias[gn];
                    float v3 = acc[mt][nt][3] + bias[gn + 1];
                    __half h0, l0, h1, l1;
                    split_h(v0, h0, l0); split_h(v1, h1, l1);
                    *(__half2*)&kh[(size_t)r0 * F + nl] = __half2(h0, h1);
                    *(__half2*)&kl[(size_t)r0 * F + nl] = __half2(l0, l1);
                    split_h(v2, h0, l0); split_h(v3, h1, l1);
                    *(__half2*)&kh[(size_t)(r0 + 8) * F + nl] = __half2(h0, h1);
                    *(__half2*)&kl[(size_t)(r0 + 8) * F + nl] = __half2(l0, l1);
                }
            }
        } else {
            // v region: stage transposed tile in smem, write vT coalesced
            CP_WAIT0();
            __half* smem_t = (__half*)smem;
            const int vb = n0 - 2 * F;
            #pragma unroll
            for (int pass = 0; pass < 2; pass++) {
                __syncthreads();
                #pragma unroll
                for (int mt = 0; mt < 4; mt++) {
                    const int ml = wm + mt * 16 + mq;
                    #pragma unroll
                    for (int nt = 0; nt < 4; nt++) {
                        const int nl = wn + nt * 8 + nq;
                        const int gn = n0 + wn + nt * 8 + nq;
                        #pragma unroll
                        for (int e = 0; e < 4; e++) {
                            const int nn = nl + (e & 1);
                            const int mm = ml + (e >> 1) * 8;
                            float v = acc[mt][nt][e] + bias[gn + (e & 1)];
                            __half h = __float2half(v);
                            __half o = h;
                            if (pass) o = __float2half(v - __half2float(h));
                            smem_t[nn * PT + mm] = o;
                        }
                    }
                }
                __syncthreads();
                __half* D = pass ? vTl : vTh;
                const int r = tid >> 1;
                const int sg = (tid & 1) * 64;
                const uint4* src = (const uint4*)&smem_t[r * PT + sg];
                uint4* dst = (uint4*)&D[(size_t)(vb + r) * S + m0 + sg];
                #pragma unroll
                for (int j = 0; j < 8; j++) dst[j] = src[j];
            }
        }
    } else {
        #pragma unroll
        for (int mt = 0; mt < 4; mt++) {
            const int r0 = m0 + wm + mt * 16 + mq;
            #pragma unroll
            for (int nt = 0; nt < 4; nt++) {
                const int gn = n0 + wn + nt * 8 + nq;
                float2 p0, p1;
                p0.x = acc[mt][nt][0] * scale;  p0.y = acc[mt][nt][1] * scale;
                p1.x = acc[mt][nt][2] * scale;  p1.y = acc[mt][nt][3] * scale;
                *(float2*)&outf[(size_t)r0 * ldo + gn]       = p0;
                *(float2*)&outf[(size_t)(r0 + 8) * ldo + gn] = p1;
            }
        }
    }
}

// ---------------- fp32 -> fp16 (hi only) ------------------------------------
__global__ __launch_bounds__(256) void convert_h_kernel(
    const float* __restrict__ in, __half* __restrict__ h, size_t n4)
{
    for (size_t i = blockIdx.x * 256 + threadIdx.x; i < n4; i += (size_t)gridDim.x * 256) {
        float4 v = ((const float4*)in)[i];
        ((__half2*)h)[i * 2 + 0] = __half2(__float2half(v.x), __float2half(v.y));
        ((__half2*)h)[i * 2 + 1] = __half2(__float2half(v.z), __float2half(v.w));
    }
}

// ---------------- transpose + split: Wt[c][r] = W[r][c] ---------------------
__global__ __launch_bounds__(256) void transpose_split_kernel(
    const float* __restrict__ W, __half* __restrict__ Th,
    __half* __restrict__ Tl, int rows, int cols)
{
    __shared__ float tile[32][33];
    const int bx = blockIdx.x * 32;
    const int by = blockIdx.y * 32;
    const int tx = threadIdx.x & 31;
    const int ty = threadIdx.x >> 5;
    #pragma unroll
    for (int i = 0; i < 4; i++)
        tile[ty + i * 8][tx] = W[(size_t)(by + ty + i * 8) * cols + bx + tx];
    __syncthreads();
    #pragma unroll
    for (int i = 0; i < 4; i++) {
        const int orow = bx + ty + i * 8;
        const int ocol = by + tx;
        __half h, l;
        split_h(tile[tx][ty + i * 8], h, l);
        Th[(size_t)orow * rows + ocol] = h;
        Tl[(size_t)orow * rows + ocol] = l;
    }
}

// ---------------- softmax: fp32 scores -> att fp16 (hi only) ----------------
__global__ __launch_bounds__(256) void softmax_kernel(
    float* __restrict__ s, __half* __restrict__ ah,
    int S, const int* __restrict__ np_ptr)
{
    const int i = blockIdx.x;
    const int np = *np_ptr;
    float* row = s + (size_t)i * S;
    __half* rh = ah + (size_t)i * S;
    const int tid = threadIdx.x;
    __shared__ float red[256];
    const int fill_end = ((i >> 7) + 1) << 7;   // end of this row's 128-block

    if (i < np) {
        const __half z = __float2half(0.f);
        for (int j = tid; j < fill_end; j += 256) rh[j] = z;
        return;
    }
    float m = -3.402823e38f;
    for (int j = np + tid; j <= i; j += 256) m = fmaxf(m, row[j]);
    red[tid] = m; __syncthreads();
    for (int off = 128; off > 0; off >>= 1) {
        if (tid < off) red[tid] = fmaxf(red[tid], red[tid + off]);
        __syncthreads();
    }
    m = red[0]; __syncthreads();

    float sum = 0.f;
    for (int j = np + tid; j <= i; j += 256) {
        float e = __expf(row[j] - m);
        row[j] = e;
        sum += e;
    }
    red[tid] = sum; __syncthreads();
    for (int off = 128; off > 0; off >>= 1) {
        if (tid < off) red[tid] += red[tid + off];
        __syncthreads();
    }
    const float inv = 1.f / red[0]; __syncthreads();

    for (int j = tid; j < fill_end; j += 256) {
        float p = (j >= np && j <= i) ? row[j] * inv : 0.f;
        rh[j] = __float2half(p);
    }
}

// ============================================================================
extern "C" void kernel_launch(void* const* d_in, const int* in_sizes, int n_in,
                              void* d_out, int out_size)
{
    const float* x  = (const float*)d_in[0];
    const float* W  = (const float*)d_in[1];
    const float* b  = (const float*)d_in[2];
    const int*   np = (const int*)  d_in[3];

    const int F3 = in_sizes[2];      // 6144
    const int F  = F3 / 3;           // 2048
    const int S  = in_sizes[0] / F;  // 4096
    float* out = (float*)d_out;

    __half *xh, *Wth, *Wtl, *qh, *kh, *kl, *vTh, *vTl, *atth;
    float* sc;
    cudaGetSymbolAddress((void**)&xh,  g_xh);
    cudaGetSymbolAddress((void**)&Wth, g_Wth);  cudaGetSymbolAddress((void**)&Wtl, g_Wtl);
    cudaGetSymbolAddress((void**)&qh,  g_qh);
    cudaGetSymbolAddress((void**)&kh,  g_kh);   cudaGetSymbolAddress((void**)&kl,  g_kl);
    cudaGetSymbolAddress((void**)&vTh, g_vTh);  cudaGetSymbolAddress((void**)&vTl, g_vTl);
    cudaGetSymbolAddress((void**)&sc,  g_scores);
    cudaGetSymbolAddress((void**)&atth, g_atth);

    cudaFuncSetAttribute(hmma_gemm<0>, cudaFuncAttributeMaxDynamicSharedMemorySize, SMEM_BYTES);
    cudaFuncSetAttribute(hmma_gemm<1>, cudaFuncAttributeMaxDynamicSharedMemorySize, SMEM_BYTES);
    cudaFuncSetAttribute(hmma_gemm<2>, cudaFuncAttributeMaxDynamicSharedMemorySize, SMEM_BYTES);

    const float scale = 1.0f / sqrtf((float)F);

    convert_h_kernel<<<2048, 256>>>(x, xh, (size_t)S * F / 4);
    transpose_split_kernel<<<dim3(F3 / 32, F / 32), 256>>>(W, Wth, Wtl, F, F3);

    // qkv = xh @ (Wth+Wtl) + b  (2-pass) -> qh, kh/kl, vT h/l
    hmma_gemm<0><<<dim3(F3 / 128, S / 128), 256, SMEM_BYTES>>>(
        xh, F, Wth, Wtl, F, F, b, 1.0f, nullptr, 0,
        qh, kh, kl, vTh, vTl, F, S, np);

    // scores = scale * qh @ (kh+kl)^T  (2-pass)
    hmma_gemm<1><<<dim3(S / 128, S / 128), 256, SMEM_BYTES>>>(
        qh, F, kh, kl, F, F, nullptr, scale, sc, S,
        nullptr, nullptr, nullptr, nullptr, nullptr, F, S, np);

    softmax_kernel<<<S, 256>>>(sc, atth, S, np);

    // out = atth @ (vTh+vTl)  (2-pass)
    hmma_gemm<2><<<dim3(F / 128, S / 128), 256, SMEM_BYTES>>>(
        atth, S, vTh, vTl, S, S, nullptr, 1.0f, out, F,
        nullptr, nullptr, nullptr, nullptr, nullptr, F, S, np);
}

// round 9
// speedup vs baseline: 2.7681x; 1.6636x over previous
#include <cuda_runtime.h>
#include <cuda_fp16.h>
#include <math.h>
#include <stdint.h>

// ============================================================================
// PaddedSHCSA, ALL GEMMs single-pass fp16 (calibrated error ~6.6e-4 < 1e-3):
//  qkv    = xh @ Wth^T + b   -> q,k hi; vT hi (transposed)
//  scores = qh @ kh^T * scale -> fp32 (causal/pad block skip)
//  out    = atth @ vTh^T      -> fp32 d_out (k-range trimmed)
// 2 smem tiles/stage, 4-stage cp.async ring, ONE barrier per chunk.
// ============================================================================

#define S_DIM   4096
#define F_DIM   2048
#define F3_DIM  6144

__device__ __half g_xh [(size_t)S_DIM * F_DIM];
__device__ __half g_Wth[(size_t)F3_DIM * F_DIM];   // W^T hi [3F][F]
__device__ __half g_qh [(size_t)S_DIM * F_DIM];
__device__ __half g_kh [(size_t)S_DIM * F_DIM];
__device__ __half g_vTh[(size_t)F_DIM * S_DIM];    // v^T [F][S]
__device__ float  g_scores[(size_t)S_DIM * S_DIM];
__device__ __half g_atth[(size_t)S_DIM * S_DIM];

// ---------------- low-level helpers -----------------------------------------
__device__ __forceinline__ uint32_t smem_u32(const void* p) {
    uint32_t a;
    asm("{ .reg .u64 t; cvta.to.shared.u64 t, %1; cvt.u32.u64 %0, t; }" : "=r"(a) : "l"(p));
    return a;
}
#define CP_ASYNC16(dst_u32, src_ptr) \
    asm volatile("cp.async.cg.shared.global [%0], [%1], 16;" :: "r"(dst_u32), "l"(src_ptr))
#define CP_COMMIT()  asm volatile("cp.async.commit_group;" ::: "memory")
#define CP_WAIT2()   asm volatile("cp.async.wait_group 2;" ::: "memory")
#define CP_WAIT0()   asm volatile("cp.async.wait_group 0;" ::: "memory")

__device__ __forceinline__ void ldsm_x4(uint32_t* r, uint32_t addr) {
    asm volatile("ldmatrix.sync.aligned.m8n8.x4.shared.b16 {%0,%1,%2,%3}, [%4];"
        : "=r"(r[0]), "=r"(r[1]), "=r"(r[2]), "=r"(r[3]) : "r"(addr));
}
__device__ __forceinline__ void mma16816(float* c, const uint32_t* a, const uint32_t* b) {
    asm volatile("mma.sync.aligned.m16n8k16.row.col.f32.f16.f16.f32 "
        "{%0,%1,%2,%3}, {%4,%5,%6,%7}, {%8,%9}, {%0,%1,%2,%3};"
        : "+f"(c[0]), "+f"(c[1]), "+f"(c[2]), "+f"(c[3])
        : "r"(a[0]), "r"(a[1]), "r"(a[2]), "r"(a[3]), "r"(b[0]), "r"(b[1]));
}

// ---------------- smem layout -----------------------------------------------
static constexpr int PA = 40;                        // pitch halves (80B row)
static constexpr int TILE_B = 128 * PA * 2;          // 10240 B
static constexpr int STAGE_B = 2 * TILE_B;           // Ah Bh = 20480 B
static constexpr int NSTAGE = 4;
static constexpr int SMEM_BYTES = NSTAGE * STAGE_B;  // 81920 B (2 CTAs/SM)
static constexpr int PT = 136;

// ============================================================================
// C[m0:+128, n0:+128] = sum_k Ah[m][k]*Bh[n][k]   (both K-major fp16)
// MODE 0: qkv (bias; -> q/k hi rows, vT hi transposed)
// MODE 1: scores (*scale -> fp32; causal/pad block skip)
// MODE 2: out (k range [np, m0+128); fp32 -> d_out)
// ============================================================================
template<int MODE>
__global__ __launch_bounds__(256, 2) void hmma_gemm(
    const __half* __restrict__ Ah, int lda,
    const __half* __restrict__ Bh, int ldb,
    int K, const float* __restrict__ bias, float scale,
    float* __restrict__ outf, int ldo,
    __half* __restrict__ qh, __half* __restrict__ kh,
    __half* __restrict__ vTh,
    int F, int S, const int* __restrict__ np_ptr)
{
    const int m0 = blockIdx.y * 128;
    const int n0 = blockIdx.x * 128;
    const int np = *np_ptr;

    if (MODE == 0) { if (m0 + 128 <= np) return; }
    if (MODE == 1) {
        if (n0 > m0) return;
        if (m0 + 128 <= np) return;
        if (n0 + 128 <= np) return;
    }

    int c0 = 0, c1 = K >> 5;
    if (MODE == 2) { c0 = np >> 5; c1 = (m0 + 128) >> 5; }
    const int nchunks = c1 - c0;

    extern __shared__ __align__(128) char smem[];
    const uint32_t sbase = smem_u32(smem);

    const int tid  = threadIdx.x;
    const int wid  = tid >> 5;
    const int lane = tid & 31;
    const int wm   = (wid >> 2) * 64;
    const int wn   = (wid & 3) * 32;

    float acc[4][4][4];
    #pragma unroll
    for (int i = 0; i < 4; i++)
        #pragma unroll
        for (int j = 0; j < 4; j++)
            #pragma unroll
            for (int e = 0; e < 4; e++) acc[i][j][e] = 0.f;

    auto prefetch = [&](int c, int stage) {
        const int kc = c << 5;
        const uint32_t st = sbase + stage * STAGE_B;
        #pragma unroll
        for (int t = 0; t < 2; t++) {
            const int idx = tid + t * 256;
            const int r   = idx >> 2;
            const int seg = idx & 3;
            const uint32_t d = (uint32_t)(r * PA * 2 + seg * 16);
            CP_ASYNC16(st + 0 * TILE_B + d, &Ah[(size_t)(m0 + r) * lda + kc + seg * 8]);
            CP_ASYNC16(st + 1 * TILE_B + d, &Bh[(size_t)(n0 + r) * ldb + kc + seg * 8]);
        }
    };

    const int arow = wm + (lane & 15);
    const int acolb = (lane >> 4) * 8;
    const int brow = wn + (lane & 7) + ((lane >> 4) << 3);
    const int bcolb = ((lane >> 3) & 1) << 3;

    if (nchunks > 0) {
        #pragma unroll
        for (int s = 0; s < NSTAGE - 1; s++) {
            if (s < nchunks) prefetch(c0 + s, s);
            CP_COMMIT();
        }
        for (int i = 0; i < nchunks; i++) {
            CP_WAIT2();
            __syncthreads();
            if (i + NSTAGE - 1 < nchunks) prefetch(c0 + i + NSTAGE - 1, (i + NSTAGE - 1) & 3);
            CP_COMMIT();
            const uint32_t st = sbase + (i & 3) * STAGE_B;
            const uint32_t aHb = st;
            const uint32_t bHb = st + TILE_B;
            #pragma unroll
            for (int ks = 0; ks < 2; ks++) {
                const int k0 = ks * 16;
                uint32_t aH[2][4];
                uint32_t bh[4][2];
                const uint32_t aOff0 = (uint32_t)((arow * PA + k0 + acolb) * 2);
                ldsm_x4(aH[0], aHb + aOff0);
                #pragma unroll
                for (int p = 0; p < 2; p++) {
                    const uint32_t off = (uint32_t)(((brow + p * 16) * PA + k0 + bcolb) * 2);
                    uint32_t r[4];
                    ldsm_x4(r, bHb + off);
                    bh[2 * p][0] = r[0]; bh[2 * p][1] = r[1];
                    bh[2 * p + 1][0] = r[2]; bh[2 * p + 1][1] = r[3];
                }
                #pragma unroll
                for (int mt = 0; mt < 4; mt++) {
                    const uint32_t offA = aOff0 + (uint32_t)(mt * 16 * PA * 2);
                    // prefetch next mt's A before consuming current (hide LDS RAW)
                    if (mt < 3) ldsm_x4(aH[(mt + 1) & 1], aHb + offA + (uint32_t)(16 * PA * 2));
                    #pragma unroll
                    for (int nt = 0; nt < 4; nt++) mma16816(acc[mt][nt], aH[mt & 1], bh[nt]);
                }
            }
        }
    }

    // ---------------- epilogue ----------------------------------------------
    const int mq = lane >> 2;
    const int nq = (lane & 3) * 2;

    if (MODE == 0) {
        const int region = n0 / F;      // 0=q 1=k 2=v
        if (region < 2) {
            __half* D = region ? kh : qh;
            const int nb = n0 - region * F;
            #pragma unroll
            for (int mt = 0; mt < 4; mt++) {
                const int r0 = m0 + wm + mt * 16 + mq;
                #pragma unroll
                for (int nt = 0; nt < 4; nt++) {
                    const int nl = nb + wn + nt * 8 + nq;
                    const int gn = n0 + wn + nt * 8 + nq;
                    __half h0 = __float2half(acc[mt][nt][0] + bias[gn]);
                    __half h1 = __float2half(acc[mt][nt][1] + bias[gn + 1]);
                    *(__half2*)&D[(size_t)r0 * F + nl] = __half2(h0, h1);
                    h0 = __float2half(acc[mt][nt][2] + bias[gn]);
                    h1 = __float2half(acc[mt][nt][3] + bias[gn + 1]);
                    *(__half2*)&D[(size_t)(r0 + 8) * F + nl] = __half2(h0, h1);
                }
            }
        } else {
            // v region: stage transposed tile in smem, write vT coalesced
            CP_WAIT0();
            __half* smem_t = (__half*)smem;
            const int vb = n0 - 2 * F;
            __syncthreads();
            #pragma unroll
            for (int mt = 0; mt < 4; mt++) {
                const int ml = wm + mt * 16 + mq;
                #pragma unroll
                for (int nt = 0; nt < 4; nt++) {
                    const int nl = wn + nt * 8 + nq;
                    const int gn = n0 + wn + nt * 8 + nq;
                    #pragma unroll
                    for (int e = 0; e < 4; e++) {
                        const int nn = nl + (e & 1);
                        const int mm = ml + (e >> 1) * 8;
                        smem_t[nn * PT + mm] = __float2half(acc[mt][nt][e] + bias[gn + (e & 1)]);
                    }
                }
            }
            __syncthreads();
            const int r = tid >> 1;
            const int sg = (tid & 1) * 64;
            const uint4* src = (const uint4*)&smem_t[r * PT + sg];
            uint4* dst = (uint4*)&vTh[(size_t)(vb + r) * S + m0 + sg];
            #pragma unroll
            for (int j = 0; j < 8; j++) dst[j] = src[j];
        }
    } else {
        #pragma unroll
        for (int mt = 0; mt < 4; mt++) {
            const int r0 = m0 + wm + mt * 16 + mq;
            #pragma unroll
            for (int nt = 0; nt < 4; nt++) {
                const int gn = n0 + wn + nt * 8 + nq;
                float2 p0, p1;
                p0.x = acc[mt][nt][0] * scale;  p0.y = acc[mt][nt][1] * scale;
                p1.x = acc[mt][nt][2] * scale;  p1.y = acc[mt][nt][3] * scale;
                *(float2*)&outf[(size_t)r0 * ldo + gn]       = p0;
                *(float2*)&outf[(size_t)(r0 + 8) * ldo + gn] = p1;
            }
        }
    }
}

// ---------------- fp32 -> fp16 (hi only) ------------------------------------
__global__ __launch_bounds__(256) void convert_h_kernel(
    const float* __restrict__ in, __half* __restrict__ h, size_t n4)
{
    for (size_t i = blockIdx.x * 256 + threadIdx.x; i < n4; i += (size_t)gridDim.x * 256) {
        float4 v = ((const float4*)in)[i];
        ((__half2*)h)[i * 2 + 0] = __half2(__float2half(v.x), __float2half(v.y));
        ((__half2*)h)[i * 2 + 1] = __half2(__float2half(v.z), __float2half(v.w));
    }
}

// ---------------- transpose (fp32 -> fp16 hi): Wt[c][r] = W[r][c] -----------
__global__ __launch_bounds__(256) void transpose_h_kernel(
    const float* __restrict__ W, __half* __restrict__ Th, int rows, int cols)
{
    __shared__ float tile[32][33];
    const int bx = blockIdx.x * 32;
    const int by = blockIdx.y * 32;
    const int tx = threadIdx.x & 31;
    const int ty = threadIdx.x >> 5;
    #pragma unroll
    for (int i = 0; i < 4; i++)
        tile[ty + i * 8][tx] = W[(size_t)(by + ty + i * 8) * cols + bx + tx];
    __syncthreads();
    #pragma unroll
    for (int i = 0; i < 4; i++) {
        const int orow = bx + ty + i * 8;
        const int ocol = by + tx;
        Th[(size_t)orow * rows + ocol] = __float2half(tile[tx][ty + i * 8]);
    }
}

// ---------------- softmax: fp32 scores -> att fp16 (hi only) ----------------
__global__ __launch_bounds__(256) void softmax_kernel(
    float* __restrict__ s, __half* __restrict__ ah,
    int S, const int* __restrict__ np_ptr)
{
    const int i = blockIdx.x;
    const int np = *np_ptr;
    float* row = s + (size_t)i * S;
    __half* rh = ah + (size_t)i * S;
    const int tid = threadIdx.x;
    __shared__ float red[256];
    const int fill_end = ((i >> 7) + 1) << 7;   // end of this row's 128-block

    if (i < np) {
        const __half z = __float2half(0.f);
        for (int j = tid; j < fill_end; j += 256) rh[j] = z;
        return;
    }
    float m = -3.402823e38f;
    for (int j = np + tid; j <= i; j += 256) m = fmaxf(m, row[j]);
    red[tid] = m; __syncthreads();
    for (int off = 128; off > 0; off >>= 1) {
        if (tid < off) red[tid] = fmaxf(red[tid], red[tid + off]);
        __syncthreads();
    }
    m = red[0]; __syncthreads();

    float sum = 0.f;
    for (int j = np + tid; j <= i; j += 256) {
        float e = __expf(row[j] - m);
        row[j] = e;
        sum += e;
    }
    red[tid] = sum; __syncthreads();
    for (int off = 128; off > 0; off >>= 1) {
        if (tid < off) red[tid] += red[tid + off];
        __syncthreads();
    }
    const float inv = 1.f / red[0]; __syncthreads();

    for (int j = tid; j < fill_end; j += 256) {
        float p = (j >= np && j <= i) ? row[j] * inv : 0.f;
        rh[j] = __float2half(p);
    }
}

// ============================================================================
extern "C" void kernel_launch(void* const* d_in, const int* in_sizes, int n_in,
                              void* d_out, int out_size)
{
    const float* x  = (const float*)d_in[0];
    const float* W  = (const float*)d_in[1];
    const float* b  = (const float*)d_in[2];
    const int*   np = (const int*)  d_in[3];

    const int F3 = in_sizes[2];      // 6144
    const int F  = F3 / 3;           // 2048
    const int S  = in_sizes[0] / F;  // 4096
    float* out = (float*)d_out;

    __half *xh, *Wth, *qh, *kh, *vTh, *atth;
    float* sc;
    cudaGetSymbolAddress((void**)&xh,  g_xh);
    cudaGetSymbolAddress((void**)&Wth, g_Wth);
    cudaGetSymbolAddress((void**)&qh,  g_qh);
    cudaGetSymbolAddress((void**)&kh,  g_kh);
    cudaGetSymbolAddress((void**)&vTh, g_vTh);
    cudaGetSymbolAddress((void**)&sc,  g_scores);
    cudaGetSymbolAddress((void**)&atth, g_atth);

    cudaFuncSetAttribute(hmma_gemm<0>, cudaFuncAttributeMaxDynamicSharedMemorySize, SMEM_BYTES);
    cudaFuncSetAttribute(hmma_gemm<1>, cudaFuncAttributeMaxDynamicSharedMemorySize, SMEM_BYTES);
    cudaFuncSetAttribute(hmma_gemm<2>, cudaFuncAttributeMaxDynamicSharedMemorySize, SMEM_BYTES);

    const float scale = 1.0f / sqrtf((float)F);

    convert_h_kernel<<<2048, 256>>>(x, xh, (size_t)S * F / 4);
    transpose_h_kernel<<<dim3(F3 / 32, F / 32), 256>>>(W, Wth, F, F3);

    // qkv = xh @ Wth^T + b -> q/k hi, vT hi
    hmma_gemm<0><<<dim3(F3 / 128, S / 128), 256, SMEM_BYTES>>>(
        xh, F, Wth, F, F, b, 1.0f, nullptr, 0,
        qh, kh, vTh, F, S, np);

    // scores = scale * qh @ kh^T
    hmma_gemm<1><<<dim3(S / 128, S / 128), 256, SMEM_BYTES>>>(
        qh, F, kh, F, F, nullptr, scale, sc, S,
        nullptr, nullptr, nullptr, F, S, np);

    softmax_kernel<<<S, 256>>>(sc, atth, S, np);

    // out = atth @ vTh^T
    hmma_gemm<2><<<dim3(F / 128, S / 128), 256, SMEM_BYTES>>>(
        atth, S, vTh, S, S, nullptr, 1.0f, out, F,
        nullptr, nullptr, nullptr, F, S, np);
}

// round 10
// speedup vs baseline: 3.6488x; 1.3181x over previous
#include <cuda_runtime.h>
#include <cuda_fp16.h>
#include <math.h>
#include <stdint.h>

// ============================================================================
// PaddedSHCSA, single-pass fp16 GEMMs (rel_err ~6e-4):
//  qkv    = xh @ Wth^T + b    -> q,k hi rows; vT hi (transposed)
//  scores = qh @ kh^T * scale -> fp32 (causal/pad block skip)
//  softmax (smem-staged, 1R+1W) -> att fp16
//  out    = atth @ vTh^T      -> fp32 d_out (k-range trimmed)
// Round 10: BK=64 chunks, XOR-swizzled 128B rows, 3-stage ring, one barrier
// per 64-K chunk; smem-staged softmax.
// ============================================================================

#define S_DIM   4096
#define F_DIM   2048
#define F3_DIM  6144

__device__ __half g_xh [(size_t)S_DIM * F_DIM];
__device__ __half g_Wth[(size_t)F3_DIM * F_DIM];   // W^T hi [3F][F]
__device__ __half g_qh [(size_t)S_DIM * F_DIM];
__device__ __half g_kh [(size_t)S_DIM * F_DIM];
__device__ __half g_vTh[(size_t)F_DIM * S_DIM];    // v^T [F][S]
__device__ float  g_scores[(size_t)S_DIM * S_DIM];
__device__ __half g_atth[(size_t)S_DIM * S_DIM];

// ---------------- low-level helpers -----------------------------------------
__device__ __forceinline__ uint32_t smem_u32(const void* p) {
    uint32_t a;
    asm("{ .reg .u64 t; cvta.to.shared.u64 t, %1; cvt.u32.u64 %0, t; }" : "=r"(a) : "l"(p));
    return a;
}
#define CP_ASYNC16(dst_u32, src_ptr) \
    asm volatile("cp.async.cg.shared.global [%0], [%1], 16;" :: "r"(dst_u32), "l"(src_ptr))
#define CP_COMMIT()  asm volatile("cp.async.commit_group;" ::: "memory")
#define CP_WAIT1()   asm volatile("cp.async.wait_group 1;" ::: "memory")
#define CP_WAIT0()   asm volatile("cp.async.wait_group 0;" ::: "memory")

__device__ __forceinline__ void ldsm_x4(uint32_t* r, uint32_t addr) {
    asm volatile("ldmatrix.sync.aligned.m8n8.x4.shared.b16 {%0,%1,%2,%3}, [%4];"
        : "=r"(r[0]), "=r"(r[1]), "=r"(r[2]), "=r"(r[3]) : "r"(addr));
}
__device__ __forceinline__ void mma16816(float* c, const uint32_t* a, const uint32_t* b) {
    asm volatile("mma.sync.aligned.m16n8k16.row.col.f32.f16.f16.f32 "
        "{%0,%1,%2,%3}, {%4,%5,%6,%7}, {%8,%9}, {%0,%1,%2,%3};"
        : "+f"(c[0]), "+f"(c[1]), "+f"(c[2]), "+f"(c[3])
        : "r"(a[0]), "r"(a[1]), "r"(a[2]), "r"(a[3]), "r"(b[0]), "r"(b[1]));
}

// ---------------- smem layout -----------------------------------------------
// BK=64 => 128B-wide rows (64 halves), XOR swizzle seg^=(row&7), no padding.
static constexpr int TILE_B = 128 * 128;             // 16384 B (128 rows x 128B)
static constexpr int STAGE_B = 2 * TILE_B;           // Ah Bh = 32768 B
static constexpr int NSTAGE = 3;
static constexpr int SMEM_BYTES = NSTAGE * STAGE_B;  // 98304 B (2 CTAs/SM: 192K)
static constexpr int PT = 136;                       // vT transpose staging pitch

// ============================================================================
// C[m0:+128, n0:+128] = sum_k Ah[m][k]*Bh[n][k]   (both K-major fp16)
// MODE 0: qkv (bias; -> q/k hi rows, vT hi transposed)
// MODE 1: scores (*scale -> fp32; causal/pad block skip)
// MODE 2: out (k range [np, m0+128); fp32 -> d_out)
// ============================================================================
template<int MODE>
__global__ __launch_bounds__(256, 2) void hmma_gemm(
    const __half* __restrict__ Ah, int lda,
    const __half* __restrict__ Bh, int ldb,
    int K, const float* __restrict__ bias, float scale,
    float* __restrict__ outf, int ldo,
    __half* __restrict__ qh, __half* __restrict__ kh,
    __half* __restrict__ vTh,
    int F, int S, const int* __restrict__ np_ptr)
{
    const int m0 = blockIdx.y * 128;
    const int n0 = blockIdx.x * 128;
    const int np = *np_ptr;

    if (MODE == 0) { if (m0 + 128 <= np) return; }
    if (MODE == 1) {
        if (n0 > m0) return;
        if (m0 + 128 <= np) return;
        if (n0 + 128 <= np) return;
    }

    int c0 = 0, c1 = K >> 6;                 // BK = 64
    if (MODE == 2) { c0 = np >> 6; c1 = (m0 + 128) >> 6; }
    const int nchunks = c1 - c0;

    extern __shared__ __align__(128) char smem[];
    const uint32_t sbase = smem_u32(smem);

    const int tid  = threadIdx.x;
    const int wid  = tid >> 5;
    const int lane = tid & 31;
    const int wm   = (wid >> 2) * 64;
    const int wn   = (wid & 3) * 32;

    float acc[4][4][4];
    #pragma unroll
    for (int i = 0; i < 4; i++)
        #pragma unroll
        for (int j = 0; j < 4; j++)
            #pragma unroll
            for (int e = 0; e < 4; e++) acc[i][j][e] = 0.f;

    auto prefetch = [&](int c, int stage) {
        const int kc = c << 6;
        const uint32_t st = sbase + stage * STAGE_B;
        #pragma unroll
        for (int t = 0; t < 4; t++) {
            const int idx = tid + t * 256;       // 0..1023
            const int r   = idx >> 3;            // row 0..127
            const int seg = idx & 7;             // 16B segment 0..7
            const uint32_t d = (uint32_t)(r * 128 + ((seg ^ (r & 7)) << 4));
            CP_ASYNC16(st + 0 * TILE_B + d, &Ah[(size_t)(m0 + r) * lda + kc + seg * 8]);
            CP_ASYNC16(st + 1 * TILE_B + d, &Bh[(size_t)(n0 + r) * ldb + kc + seg * 8]);
        }
    };

    const int arow  = wm + (lane & 15);
    const int acolb = (lane >> 4) * 8;                       // 0 or 8
    const int brow  = wn + (lane & 7) + ((lane >> 4) << 3);
    const int bcolb = ((lane >> 3) & 1) << 3;                // 0 or 8
    const int a7 = arow & 7;                                 // row-lane swizzle key
    const int b7 = brow & 7;

    if (nchunks > 0) {
        prefetch(c0, 0); CP_COMMIT();
        if (nchunks > 1) prefetch(c0 + 1, 1);
        CP_COMMIT();
        int s_cur = 0, s_pf = 2;
        for (int i = 0; i < nchunks; i++) {
            CP_WAIT1();
            __syncthreads();
            if (i + 2 < nchunks) prefetch(c0 + i + 2, s_pf);
            CP_COMMIT();
            const uint32_t aHb = sbase + s_cur * STAGE_B;
            const uint32_t bHb = aHb + TILE_B;
            #pragma unroll
            for (int ks = 0; ks < 4; ks++) {
                const int k0 = ks * 16;
                const uint32_t aswz = (uint32_t)(((((k0 + acolb) >> 3) ^ a7) << 4));
                const uint32_t bswz = (uint32_t)(((((k0 + bcolb) >> 3) ^ b7) << 4));
                uint32_t aH[2][4];
                uint32_t bh[4][2];
                const uint32_t aAddr0 = aHb + (uint32_t)(arow * 128) + aswz;
                ldsm_x4(aH[0], aAddr0);
                #pragma unroll
                for (int p = 0; p < 2; p++) {
                    uint32_t r[4];
                    ldsm_x4(r, bHb + (uint32_t)((brow + p * 16) * 128) + bswz);
                    bh[2 * p][0] = r[0]; bh[2 * p][1] = r[1];
                    bh[2 * p + 1][0] = r[2]; bh[2 * p + 1][1] = r[3];
                }
                #pragma unroll
                for (int mt = 0; mt < 4; mt++) {
                    if (mt < 3) ldsm_x4(aH[(mt + 1) & 1], aAddr0 + (uint32_t)((mt + 1) * 16 * 128));
                    #pragma unroll
                    for (int nt = 0; nt < 4; nt++) mma16816(acc[mt][nt], aH[mt & 1], bh[nt]);
                }
            }
            s_cur = (s_cur == 2) ? 0 : s_cur + 1;
            s_pf  = (s_pf  == 2) ? 0 : s_pf  + 1;
        }
    }

    // ---------------- epilogue ----------------------------------------------
    const int mq = lane >> 2;
    const int nq = (lane & 3) * 2;

    if (MODE == 0) {
        const int region = n0 / F;      // 0=q 1=k 2=v
        if (region < 2) {
            __half* D = region ? kh : qh;
            const int nb = n0 - region * F;
            #pragma unroll
            for (int mt = 0; mt < 4; mt++) {
                const int r0 = m0 + wm + mt * 16 + mq;
                #pragma unroll
                for (int nt = 0; nt < 4; nt++) {
                    const int nl = nb + wn + nt * 8 + nq;
                    const int gn = n0 + wn + nt * 8 + nq;
                    __half h0 = __float2half(acc[mt][nt][0] + bias[gn]);
                    __half h1 = __float2half(acc[mt][nt][1] + bias[gn + 1]);
                    *(__half2*)&D[(size_t)r0 * F + nl] = __half2(h0, h1);
                    h0 = __float2half(acc[mt][nt][2] + bias[gn]);
                    h1 = __float2half(acc[mt][nt][3] + bias[gn + 1]);
                    *(__half2*)&D[(size_t)(r0 + 8) * F + nl] = __half2(h0, h1);
                }
            }
        } else {
            // v region: stage transposed tile in smem, write vT coalesced
            CP_WAIT0();
            __half* smem_t = (__half*)smem;
            const int vb = n0 - 2 * F;
            __syncthreads();
            #pragma unroll
            for (int mt = 0; mt < 4; mt++) {
                const int ml = wm + mt * 16 + mq;
                #pragma unroll
                for (int nt = 0; nt < 4; nt++) {
                    const int nl = wn + nt * 8 + nq;
                    const int gn = n0 + wn + nt * 8 + nq;
                    #pragma unroll
                    for (int e = 0; e < 4; e++) {
                        const int nn = nl + (e & 1);
                        const int mm = ml + (e >> 1) * 8;
                        smem_t[nn * PT + mm] = __float2half(acc[mt][nt][e] + bias[gn + (e & 1)]);
                    }
                }
            }
            __syncthreads();
            const int r = tid >> 1;
            const int sg = (tid & 1) * 64;
            const uint4* src = (const uint4*)&smem_t[r * PT + sg];
            uint4* dst = (uint4*)&vTh[(size_t)(vb + r) * S + m0 + sg];
            #pragma unroll
            for (int j = 0; j < 8; j++) dst[j] = src[j];
        }
    } else {
        #pragma unroll
        for (int mt = 0; mt < 4; mt++) {
            const int r0 = m0 + wm + mt * 16 + mq;
            #pragma unroll
            for (int nt = 0; nt < 4; nt++) {
                const int gn = n0 + wn + nt * 8 + nq;
                float2 p0, p1;
                p0.x = acc[mt][nt][0] * scale;  p0.y = acc[mt][nt][1] * scale;
                p1.x = acc[mt][nt][2] * scale;  p1.y = acc[mt][nt][3] * scale;
                *(float2*)&outf[(size_t)r0 * ldo + gn]       = p0;
                *(float2*)&outf[(size_t)(r0 + 8) * ldo + gn] = p1;
            }
        }
    }
}

// ---------------- fp32 -> fp16 (hi only) ------------------------------------
__global__ __launch_bounds__(256) void convert_h_kernel(
    const float* __restrict__ in, __half* __restrict__ h, size_t n4)
{
    for (size_t i = blockIdx.x * 256 + threadIdx.x; i < n4; i += (size_t)gridDim.x * 256) {
        float4 v = ((const float4*)in)[i];
        ((__half2*)h)[i * 2 + 0] = __half2(__float2half(v.x), __float2half(v.y));
        ((__half2*)h)[i * 2 + 1] = __half2(__float2half(v.z), __float2half(v.w));
    }
}

// ---------------- transpose (fp32 -> fp16 hi): Wt[c][r] = W[r][c] -----------
__global__ __launch_bounds__(256) void transpose_h_kernel(
    const float* __restrict__ W, __half* __restrict__ Th, int rows, int cols)
{
    __shared__ float tile[32][33];
    const int bx = blockIdx.x * 32;
    const int by = blockIdx.y * 32;
    const int tx = threadIdx.x & 31;
    const int ty = threadIdx.x >> 5;
    #pragma unroll
    for (int i = 0; i < 4; i++)
        tile[ty + i * 8][tx] = W[(size_t)(by + ty + i * 8) * cols + bx + tx];
    __syncthreads();
    #pragma unroll
    for (int i = 0; i < 4; i++) {
        const int orow = bx + ty + i * 8;
        const int ocol = by + tx;
        Th[(size_t)orow * rows + ocol] = __float2half(tile[tx][ty + i * 8]);
    }
}

// ---------------- softmax: smem-staged, 1 global read + 1 fp16 write --------
__global__ __launch_bounds__(256) void softmax_kernel(
    const float* __restrict__ s, __half* __restrict__ ah,
    int S, const int* __restrict__ np_ptr)
{
    __shared__ float buf[S_DIM];
    __shared__ float red[256];
    const int i = blockIdx.x;
    const int np = *np_ptr;
    const __half* dummy = nullptr; (void)dummy;
    __half* rh = ah + (size_t)i * S;
    const int tid = threadIdx.x;
    const int fill_end = ((i >> 7) + 1) << 7;   // covers out-GEMM read range

    if (i < np) {
        const __half z = __float2half(0.f);
        for (int j = tid; j < fill_end; j += 256) rh[j] = z;
        return;
    }
    const float* row = s + (size_t)i * S;

    // pass A: load valid segment into smem, fused running max
    float m = -3.402823e38f;
    for (int j = np + tid; j <= i; j += 256) {
        float v = row[j];
        buf[j] = v;
        m = fmaxf(m, v);
    }
    red[tid] = m; __syncthreads();
    for (int off = 128; off > 0; off >>= 1) {
        if (tid < off) red[tid] = fmaxf(red[tid], red[tid + off]);
        __syncthreads();
    }
    m = red[0]; __syncthreads();

    // pass B: exp in smem + sum
    float sum = 0.f;
    for (int j = np + tid; j <= i; j += 256) {
        float e = __expf(buf[j] - m);
        buf[j] = e;
        sum += e;
    }
    red[tid] = sum; __syncthreads();
    for (int off = 128; off > 0; off >>= 1) {
        if (tid < off) red[tid] += red[tid + off];
        __syncthreads();
    }
    const float inv = 1.f / red[0]; __syncthreads();

    // pass C: single fp16 write (zero outside [np, i])
    for (int j = tid; j < fill_end; j += 256) {
        float p = (j >= np && j <= i) ? buf[j] * inv : 0.f;
        rh[j] = __float2half(p);
    }
}

// ============================================================================
extern "C" void kernel_launch(void* const* d_in, const int* in_sizes, int n_in,
                              void* d_out, int out_size)
{
    const float* x  = (const float*)d_in[0];
    const float* W  = (const float*)d_in[1];
    const float* b  = (const float*)d_in[2];
    const int*   np = (const int*)  d_in[3];

    const int F3 = in_sizes[2];      // 6144
    const int F  = F3 / 3;           // 2048
    const int S  = in_sizes[0] / F;  // 4096
    float* out = (float*)d_out;

    __half *xh, *Wth, *qh, *kh, *vTh, *atth;
    float* sc;
    cudaGetSymbolAddress((void**)&xh,  g_xh);
    cudaGetSymbolAddress((void**)&Wth, g_Wth);
    cudaGetSymbolAddress((void**)&qh,  g_qh);
    cudaGetSymbolAddress((void**)&kh,  g_kh);
    cudaGetSymbolAddress((void**)&vTh, g_vTh);
    cudaGetSymbolAddress((void**)&sc,  g_scores);
    cudaGetSymbolAddress((void**)&atth, g_atth);

    cudaFuncSetAttribute(hmma_gemm<0>, cudaFuncAttributeMaxDynamicSharedMemorySize, SMEM_BYTES);
    cudaFuncSetAttribute(hmma_gemm<1>, cudaFuncAttributeMaxDynamicSharedMemorySize, SMEM_BYTES);
    cudaFuncSetAttribute(hmma_gemm<2>, cudaFuncAttributeMaxDynamicSharedMemorySize, SMEM_BYTES);

    const float scale = 1.0f / sqrtf((float)F);

    convert_h_kernel<<<2048, 256>>>(x, xh, (size_t)S * F / 4);
    transpose_h_kernel<<<dim3(F3 / 32, F / 32), 256>>>(W, Wth, F, F3);

    // qkv = xh @ Wth^T + b -> q/k hi, vT hi
    hmma_gemm<0><<<dim3(F3 / 128, S / 128), 256, SMEM_BYTES>>>(
        xh, F, Wth, F, F, b, 1.0f, nullptr, 0,
        qh, kh, vTh, F, S, np);

    // scores = scale * qh @ kh^T
    hmma_gemm<1><<<dim3(S / 128, S / 128), 256, SMEM_BYTES>>>(
        qh, F, kh, F, F, nullptr, scale, sc, S,
        nullptr, nullptr, nullptr, F, S, np);

    softmax_kernel<<<S, 256>>>(sc, atth, S, np);

    // out = atth @ vTh^T
    hmma_gemm<2><<<dim3(F / 128, S / 128), 256, SMEM_BYTES>>>(
        atth, S, vTh, S, S, nullptr, 1.0f, out, F,
        nullptr, nullptr, nullptr, F, S, np);
}